// round 9
// baseline (speedup 1.0000x reference)
#include <cuda_runtime.h>
#include <cuda_fp16.h>
#include <cstdint>

#define NN 200000
#define NE 800000
#define HID 256

// ---------------- device scratch (no allocations allowed) ----------------
__device__ float g_buf0[(size_t)NN * HID];
__device__ float g_buf1[(size_t)NN * HID];
__device__ float g_agg [(size_t)NN * HID];
__device__ float g_weak[NN * 4];
__device__ float g_conf[NN];
__device__ float g_p3  [NN * 4];

__device__ __forceinline__ void red_add_v4(float* dst, float4 v)
{
    asm volatile("red.global.add.v4.f32 [%0], {%1, %2, %3, %4};"
                 :: "l"(dst), "f"(v.x), "f"(v.y), "f"(v.z), "f"(v.w)
                 : "memory");
}

__device__ __forceinline__ uint32_t pack_h2(float lo, float hi)
{
    __half2 h = __floats2half2_rn(lo, hi);   // .x = lo (low 16 bits), .y = hi
    return *(uint32_t*)&h;
}

// ---------------- node preprocessing: weak expert + conf + stage-1 of h --
__global__ void node_pre_kernel(const float* __restrict__ x,
                                const float* __restrict__ w1, const float* __restrict__ b1,
                                const float* __restrict__ w2, const float* __restrict__ b2,
                                const float* __restrict__ e1, const float* __restrict__ be1)
{
    int warp = (blockIdx.x * blockDim.x + threadIdx.x) >> 5;
    int lane = threadIdx.x & 31;
    if (warp >= NN) return;

    float xs[6];
#pragma unroll
    for (int i = 0; i < 6; i++) xs[i] = __ldg(&x[warp * 10 + 4 + i]);

    float pc0 = 0.f, pc1 = 0.f, pc2 = 0.f, pc3 = 0.f;
#pragma unroll
    for (int j = 0; j < 8; j++) {
        int t = lane + 32 * j;
        float ge = __ldg(&be1[t]);
        float gw = __ldg(&b1[t]);
#pragma unroll
        for (int i = 0; i < 6; i++) {
            ge = fmaf(xs[i], __ldg(&e1[i * HID + t]), ge);
            gw = fmaf(xs[i], __ldg(&w1[i * HID + t]), gw);
        }
        ge = fmaxf(ge, 0.f);
        gw = fmaxf(gw, 0.f);
        g_buf0[(size_t)warp * HID + t] = ge;
        pc0 = fmaf(gw, __ldg(&w2[t * 4 + 0]), pc0);
        pc1 = fmaf(gw, __ldg(&w2[t * 4 + 1]), pc1);
        pc2 = fmaf(gw, __ldg(&w2[t * 4 + 2]), pc2);
        pc3 = fmaf(gw, __ldg(&w2[t * 4 + 3]), pc3);
    }
#pragma unroll
    for (int o = 16; o > 0; o >>= 1) {
        pc0 += __shfl_xor_sync(0xffffffffu, pc0, o);
        pc1 += __shfl_xor_sync(0xffffffffu, pc1, o);
        pc2 += __shfl_xor_sync(0xffffffffu, pc2, o);
        pc3 += __shfl_xor_sync(0xffffffffu, pc3, o);
    }
    if (lane == 0) {
        float wk[4];
        wk[0] = pc0 + __ldg(&b2[0]);
        wk[1] = pc1 + __ldg(&b2[1]);
        wk[2] = pc2 + __ldg(&b2[2]);
        wk[3] = pc3 + __ldg(&b2[3]);
        float m = fmaxf(fmaxf(wk[0], wk[1]), fmaxf(wk[2], wk[3]));
        float ex[4], s = 0.f;
#pragma unroll
        for (int c = 0; c < 4; c++) { ex[c] = expf(wk[c] - m); s += ex[c]; }
        float inv = 1.f / s;
        float p[4], mean = 0.f;
#pragma unroll
        for (int c = 0; c < 4; c++) { p[c] = ex[c] * inv; mean += p[c]; }
        mean *= 0.25f;
        float var = 0.f, ent = 0.f;
#pragma unroll
        for (int c = 0; c < 4; c++) {
            float d = p[c] - mean;
            var += d * d;
            ent -= p[c] * logf(p[c] + 1e-8f);
        }
        var *= 0.25f;
        ent *= (1.f / 1.3862943611198906f);  // / log(4)
        float conf = 0.5f * (var + (1.f - ent));
        conf = fminf(fmaxf(conf, 0.f), 1.f);
        g_conf[warp] = conf;
#pragma unroll
        for (int c = 0; c < 4; c++) g_weak[warp * 4 + c] = wk[c];
    }
}

// ---------------- zero kernel (float4) ----------------
__global__ void zero_kernel(float4* __restrict__ p, int n4)
{
    int i = blockIdx.x * blockDim.x + threadIdx.x;
    if (i < n4) p[i] = make_float4(0.f, 0.f, 0.f, 0.f);
}

// ---------------- edge scatter: agg[tgt] += h[src], 256-wide ----------------
__global__ void scatter_kernel(const float* __restrict__ h, float* __restrict__ agg,
                               const int* __restrict__ src,
                               const int* __restrict__ tgt)
{
    int idx = blockIdx.x * blockDim.x + threadIdx.x;  // NE*32 threads
    if (idx >= NE * 32) return;
    int e = idx >> 5;
    int c = (idx & 31) << 3;
    int s = __ldg(&src[e]);
    int t = __ldg(&tgt[e]);
    const float4* hp = (const float4*)(h + (size_t)s * HID + c);
    float4 v0 = __ldg(hp);
    float4 v1 = __ldg(hp + 1);
    float* dst = agg + (size_t)t * HID + c;
    red_add_v4(dst, v0);
    red_add_v4(dst + 4, v1);
}

// ---------------- FP16 tensor-core GEMM (m16n8k16, fp32 accumulate) -------
// C[M,256] = act(A1@B1 (+ A2@B2) + bias)
// BM=128, BN=128, BK=32 floats; 256 threads = 8 warps (2M x 4N); warp 64x32.
// Tiles stored as packed half2, k-contiguous, pitch 20 half2 (conflict-free frags).
#define BM 128
#define BN 128
#define BK 32
#define PITCH2 20     // pitch in half2 units (16 data + 4 pad)
__global__ __launch_bounds__(256) void gemm_tc_kernel(
    const float* __restrict__ A1, const float* __restrict__ B1,
    const float* __restrict__ A2, const float* __restrict__ B2,
    const float* __restrict__ bias, float* __restrict__ C,
    int relu, int dual)
{
    __shared__ uint32_t As2[BM * PITCH2];   // [row][k/2]
    __shared__ uint32_t Bs2[BN * PITCH2];   // [col][k/2]  (B transposed)

    const int tid  = threadIdx.x;
    const int warp = tid >> 5;
    const int lane = tid & 31;
    const int wm = warp & 1;         // 0..1 (M)
    const int wn = warp >> 1;        // 0..3 (N)
    const int g  = lane >> 2;        // 0..7
    const int t  = lane & 3;         // 0..3
    const int bm = blockIdx.x * BM;
    const int bn = blockIdx.y * BN;

    float acc[4][4][4];
#pragma unroll
    for (int mt = 0; mt < 4; mt++)
#pragma unroll
        for (int nt = 0; nt < 4; nt++)
#pragma unroll
            for (int c = 0; c < 4; c++) acc[mt][nt][c] = 0.f;

    const int nPass = dual ? 2 : 1;
    for (int pass = 0; pass < nPass; ++pass) {
        const float* A = pass ? A2 : A1;
        const float* B = pass ? B2 : B1;
        for (int k0 = 0; k0 < 256; k0 += BK) {
            __syncthreads();
            // A tile: 128 rows x 32 k. Each thread: 1 float4 -> 2 half2.
#pragma unroll
            for (int i = 0; i < 4; i++) {
                int idx = tid + i * 256;      // 0..1023
                int m  = idx >> 3;            // 0..127
                int kq = (idx & 7) << 2;      // 0,4,..,28 (floats)
                int gr = bm + m;
                float4 v = make_float4(0.f, 0.f, 0.f, 0.f);
                if (gr < NN)
                    v = *(const float4*)(A + (size_t)gr * 256 + k0 + kq);
                As2[m * PITCH2 + (kq >> 1)    ] = pack_h2(v.x, v.y);
                As2[m * PITCH2 + (kq >> 1) + 1] = pack_h2(v.z, v.w);
            }
            // B tile transposed: Bs2[n][k/2]. Each thread: one (n, kpair).
            // idx -> n = idx>>4 (0..127), p = idx&15 (k-pair). Coalesced in n.
#pragma unroll
            for (int i = 0; i < 8; i++) {
                int idx = tid + i * 256;      // 0..2047
                int n = idx >> 4;
                int p = idx & 15;
                float v0 = __ldg(B + (size_t)(k0 + 2 * p    ) * 256 + bn + n);
                float v1 = __ldg(B + (size_t)(k0 + 2 * p + 1) * 256 + bn + n);
                Bs2[n * PITCH2 + p] = pack_h2(v0, v1);
            }
            __syncthreads();
            // 2 x k16 steps per BK=32 chunk
#pragma unroll
            for (int kk = 0; kk < 2; kk++) {
                const int kk8 = kk * 8;      // half2 offset
                uint32_t af[4][4];
#pragma unroll
                for (int mt = 0; mt < 4; mt++) {
                    int r0 = (wm * 64 + mt * 16 + g) * PITCH2;
                    int r8 = r0 + 8 * PITCH2;
                    af[mt][0] = As2[r0 + kk8 + t];
                    af[mt][1] = As2[r8 + kk8 + t];
                    af[mt][2] = As2[r0 + kk8 + t + 4];
                    af[mt][3] = As2[r8 + kk8 + t + 4];
                }
#pragma unroll
                for (int nt = 0; nt < 4; nt++) {
                    int cc = (wn * 32 + nt * 8 + g) * PITCH2;
                    uint32_t b0 = Bs2[cc + kk8 + t];
                    uint32_t b1 = Bs2[cc + kk8 + t + 4];
#pragma unroll
                    for (int mt = 0; mt < 4; mt++) {
                        asm volatile(
                            "mma.sync.aligned.m16n8k16.row.col.f32.f16.f16.f32 "
                            "{%0,%1,%2,%3}, {%4,%5,%6,%7}, {%8,%9}, {%0,%1,%2,%3};"
                            : "+f"(acc[mt][nt][0]), "+f"(acc[mt][nt][1]),
                              "+f"(acc[mt][nt][2]), "+f"(acc[mt][nt][3])
                            : "r"(af[mt][0]), "r"(af[mt][1]),
                              "r"(af[mt][2]), "r"(af[mt][3]),
                              "r"(b0), "r"(b1));
                    }
                }
            }
        }
    }

    // epilogue: c0:(g,2t) c1:(g,2t+1) c2:(g+8,2t) c3:(g+8,2t+1)
#pragma unroll
    for (int nt = 0; nt < 4; nt++) {
        int col = bn + wn * 32 + nt * 8 + 2 * t;
        float bz0 = __ldg(&bias[col]);
        float bz1 = __ldg(&bias[col + 1]);
#pragma unroll
        for (int mt = 0; mt < 4; mt++) {
            int row0 = bm + wm * 64 + mt * 16 + g;
            float v0 = acc[mt][nt][0] + bz0;
            float v1 = acc[mt][nt][1] + bz1;
            float v2 = acc[mt][nt][2] + bz0;
            float v3 = acc[mt][nt][3] + bz1;
            if (relu) {
                v0 = fmaxf(v0, 0.f); v1 = fmaxf(v1, 0.f);
                v2 = fmaxf(v2, 0.f); v3 = fmaxf(v3, 0.f);
            }
            if (row0 < NN)
                *(float2*)(C + (size_t)row0 * 256 + col) = make_float2(v0, v1);
            if (row0 + 8 < NN)
                *(float2*)(C + (size_t)(row0 + 8) * 256 + col) = make_float2(v2, v3);
        }
    }
}

// ---------------- last layer projections + output init (exact fp32) ----
__global__ void node_post_kernel(const float* __restrict__ h,
                                 const float* __restrict__ rw3,
                                 const float* __restrict__ rb3,
                                 const float* __restrict__ sw3,
                                 float* __restrict__ out)
{
    int warp = (blockIdx.x * blockDim.x + threadIdx.x) >> 5;
    int lane = threadIdx.x & 31;
    if (warp >= NN) return;

    float pp[4] = {0.f, 0.f, 0.f, 0.f};
    float ss[4] = {0.f, 0.f, 0.f, 0.f};
#pragma unroll
    for (int j = 0; j < 8; j++) {
        int t = lane + 32 * j;
        float hv = h[(size_t)warp * HID + t];
#pragma unroll
        for (int c = 0; c < 4; c++) {
            pp[c] = fmaf(hv, __ldg(&rw3[t * 4 + c]), pp[c]);
            ss[c] = fmaf(hv, __ldg(&sw3[t * 4 + c]), ss[c]);
        }
    }
#pragma unroll
    for (int o = 16; o > 0; o >>= 1) {
#pragma unroll
        for (int c = 0; c < 4; c++) {
            pp[c] += __shfl_xor_sync(0xffffffffu, pp[c], o);
            ss[c] += __shfl_xor_sync(0xffffffffu, ss[c], o);
        }
    }
    if (lane == 0) {
        float cf = g_conf[warp];
        float om = 1.f - cf;
#pragma unroll
        for (int c = 0; c < 4; c++) {
            out[warp * 4 + c] = cf * g_weak[warp * 4 + c] + om * (ss[c] + __ldg(&rb3[c]));
            g_p3[warp * 4 + c] = pp[c];
        }
    }
}

// ---------------- final 4-wide edge scatter ----------------
__global__ void edge3_kernel(const int* __restrict__ src,
                             const int* __restrict__ tgt,
                             float* __restrict__ out)
{
    int e = blockIdx.x * blockDim.x + threadIdx.x;
    if (e >= NE) return;
    int s = __ldg(&src[e]);
    int t = __ldg(&tgt[e]);
    float om = 1.f - g_conf[t];
    float4 p = *(const float4*)&g_p3[s * 4];
    p.x *= om; p.y *= om; p.z *= om; p.w *= om;
    red_add_v4(&out[t * 4], p);
}

// ---------------- host ----------------
extern "C" void kernel_launch(void* const* d_in, const int* in_sizes, int n_in,
                              void* d_out, int out_size)
{
    const float* x   = (const float*)d_in[0];
    const int* ei    = (const int*)d_in[1];   // int32 (JAX x64 disabled)
    const float* w1  = (const float*)d_in[2];
    const float* b1  = (const float*)d_in[3];
    const float* w2  = (const float*)d_in[4];
    const float* b2  = (const float*)d_in[5];
    const float* e1  = (const float*)d_in[6];
    const float* be1 = (const float*)d_in[7];
    const float* e2  = (const float*)d_in[8];
    const float* be2 = (const float*)d_in[9];
    const float* RW[3] = {(const float*)d_in[10], (const float*)d_in[13], (const float*)d_in[16]};
    const float* RB[3] = {(const float*)d_in[11], (const float*)d_in[14], (const float*)d_in[17]};
    const float* SW[3] = {(const float*)d_in[12], (const float*)d_in[15], (const float*)d_in[18]};
    const float* rw3 = (const float*)d_in[19];
    const float* rb3 = (const float*)d_in[20];
    const float* sw3 = (const float*)d_in[21];
    float* out = (float*)d_out;

    float *buf0, *buf1, *agg;
    cudaGetSymbolAddress((void**)&buf0, g_buf0);
    cudaGetSymbolAddress((void**)&buf1, g_buf1);
    cudaGetSymbolAddress((void**)&agg,  g_agg);

    const int* src = ei;
    const int* tgt = ei + NE;

    node_pre_kernel<<<(NN * 32 + 255) / 256, 256>>>(x, w1, b1, w2, b2, e1, be1);

    dim3 gg((NN + BM - 1) / BM, 256 / BN);
    gemm_tc_kernel<<<gg, 256>>>(buf0, e2, nullptr, nullptr, be2, buf1, 0, 0);

    float* hcur = buf1;
    float* hnext = buf0;
    const int z4 = NN * (HID / 4);
    for (int l = 0; l < 3; l++) {
        zero_kernel<<<(z4 + 255) / 256, 256>>>((float4*)agg, z4);
        scatter_kernel<<<(NE * 32 + 255) / 256, 256>>>(hcur, agg, src, tgt);
        gemm_tc_kernel<<<gg, 256>>>(agg, RW[l], hcur, SW[l], RB[l], hnext, 1, 1);
        float* tmp = hcur; hcur = hnext; hnext = tmp;
    }

    node_post_kernel<<<(NN * 32 + 255) / 256, 256>>>(hcur, rw3, rb3, sw3, out);
    edge3_kernel<<<(NE + 255) / 256, 256>>>(src, tgt, out);
}

// round 10
// speedup vs baseline: 1.4567x; 1.4567x over previous
#include <cuda_runtime.h>
#include <cuda_fp16.h>
#include <cstdint>

#define NN 200000
#define NE 800000
#define HID 256

// ---------------- device scratch (no allocations allowed) ----------------
__device__ float g_buf0[(size_t)NN * HID];
__device__ float g_buf1[(size_t)NN * HID];
__device__ float g_agg [(size_t)NN * HID];
__device__ float g_weak[NN * 4];
__device__ float g_conf[NN];
__device__ float g_p3  [NN * 4];
// 7 weight matrices, transposed to [n][k], fp16: e2, rw0, sw0, rw1, sw1, rw2, sw2
__device__ __half g_wt[7 * 256 * 256];

__device__ __forceinline__ void red_add_v4(float* dst, float4 v)
{
    asm volatile("red.global.add.v4.f32 [%0], {%1, %2, %3, %4};"
                 :: "l"(dst), "f"(v.x), "f"(v.y), "f"(v.z), "f"(v.w)
                 : "memory");
}

__device__ __forceinline__ uint32_t pack_h2(float lo, float hi)
{
    __half2 h = __floats2half2_rn(lo, hi);
    return *(uint32_t*)&h;
}

// ---------------- weight prep: transpose + fp16 convert (tiny) ----------
__global__ void wprep_kernel(const float* __restrict__ e2,
                             const float* __restrict__ rw0, const float* __restrict__ sw0,
                             const float* __restrict__ rw1, const float* __restrict__ sw1,
                             const float* __restrict__ rw2, const float* __restrict__ sw2)
{
    int idx = blockIdx.x * blockDim.x + threadIdx.x;
    if (idx >= 7 * 65536) return;
    int mat = idx >> 16;
    int r   = idx & 65535;
    int n   = r >> 8;
    int k   = r & 255;
    const float* W;
    switch (mat) {
        case 0: W = e2;  break;
        case 1: W = rw0; break;
        case 2: W = sw0; break;
        case 3: W = rw1; break;
        case 4: W = sw1; break;
        case 5: W = rw2; break;
        default: W = sw2; break;
    }
    g_wt[idx] = __float2half(__ldg(&W[k * 256 + n]));
}

// ---------------- node preprocessing: weak expert + conf + stage-1 of h --
__global__ void node_pre_kernel(const float* __restrict__ x,
                                const float* __restrict__ w1, const float* __restrict__ b1,
                                const float* __restrict__ w2, const float* __restrict__ b2,
                                const float* __restrict__ e1, const float* __restrict__ be1)
{
    int warp = (blockIdx.x * blockDim.x + threadIdx.x) >> 5;
    int lane = threadIdx.x & 31;
    if (warp >= NN) return;

    float xs[6];
#pragma unroll
    for (int i = 0; i < 6; i++) xs[i] = __ldg(&x[warp * 10 + 4 + i]);

    float pc0 = 0.f, pc1 = 0.f, pc2 = 0.f, pc3 = 0.f;
#pragma unroll
    for (int j = 0; j < 8; j++) {
        int t = lane + 32 * j;
        float ge = __ldg(&be1[t]);
        float gw = __ldg(&b1[t]);
#pragma unroll
        for (int i = 0; i < 6; i++) {
            ge = fmaf(xs[i], __ldg(&e1[i * HID + t]), ge);
            gw = fmaf(xs[i], __ldg(&w1[i * HID + t]), gw);
        }
        ge = fmaxf(ge, 0.f);
        gw = fmaxf(gw, 0.f);
        g_buf0[(size_t)warp * HID + t] = ge;
        pc0 = fmaf(gw, __ldg(&w2[t * 4 + 0]), pc0);
        pc1 = fmaf(gw, __ldg(&w2[t * 4 + 1]), pc1);
        pc2 = fmaf(gw, __ldg(&w2[t * 4 + 2]), pc2);
        pc3 = fmaf(gw, __ldg(&w2[t * 4 + 3]), pc3);
    }
#pragma unroll
    for (int o = 16; o > 0; o >>= 1) {
        pc0 += __shfl_xor_sync(0xffffffffu, pc0, o);
        pc1 += __shfl_xor_sync(0xffffffffu, pc1, o);
        pc2 += __shfl_xor_sync(0xffffffffu, pc2, o);
        pc3 += __shfl_xor_sync(0xffffffffu, pc3, o);
    }
    if (lane == 0) {
        float wk[4];
        wk[0] = pc0 + __ldg(&b2[0]);
        wk[1] = pc1 + __ldg(&b2[1]);
        wk[2] = pc2 + __ldg(&b2[2]);
        wk[3] = pc3 + __ldg(&b2[3]);
        float m = fmaxf(fmaxf(wk[0], wk[1]), fmaxf(wk[2], wk[3]));
        float ex[4], s = 0.f;
#pragma unroll
        for (int c = 0; c < 4; c++) { ex[c] = expf(wk[c] - m); s += ex[c]; }
        float inv = 1.f / s;
        float p[4], mean = 0.f;
#pragma unroll
        for (int c = 0; c < 4; c++) { p[c] = ex[c] * inv; mean += p[c]; }
        mean *= 0.25f;
        float var = 0.f, ent = 0.f;
#pragma unroll
        for (int c = 0; c < 4; c++) {
            float d = p[c] - mean;
            var += d * d;
            ent -= p[c] * logf(p[c] + 1e-8f);
        }
        var *= 0.25f;
        ent *= (1.f / 1.3862943611198906f);  // / log(4)
        float conf = 0.5f * (var + (1.f - ent));
        conf = fminf(fmaxf(conf, 0.f), 1.f);
        g_conf[warp] = conf;
#pragma unroll
        for (int c = 0; c < 4; c++) g_weak[warp * 4 + c] = wk[c];
    }
}

// ---------------- zero kernel (float4) ----------------
__global__ void zero_kernel(float4* __restrict__ p, int n4)
{
    int i = blockIdx.x * blockDim.x + threadIdx.x;
    if (i < n4) p[i] = make_float4(0.f, 0.f, 0.f, 0.f);
}

// ---------------- edge scatter: agg[tgt] += h[src], 256-wide ----------------
__global__ void scatter_kernel(const float* __restrict__ h, float* __restrict__ agg,
                               const int* __restrict__ src,
                               const int* __restrict__ tgt)
{
    int idx = blockIdx.x * blockDim.x + threadIdx.x;  // NE*32 threads
    if (idx >= NE * 32) return;
    int e = idx >> 5;
    int c = (idx & 31) << 3;
    int s = __ldg(&src[e]);
    int t = __ldg(&tgt[e]);
    const float4* hp = (const float4*)(h + (size_t)s * HID + c);
    float4 v0 = __ldg(hp);
    float4 v1 = __ldg(hp + 1);
    float* dst = agg + (size_t)t * HID + c;
    red_add_v4(dst, v0);
    red_add_v4(dst + 4, v1);
}

// ---------------- FP16 tensor-core GEMM (m16n8k16, fp32 accumulate) -------
// C[M,256] = act(A1@B1t (+ A2@B2t) + bias); B*t are fp16 [n][k] pre-transposed.
// BM=128, BN=128, BK=32; 256 threads = 8 warps (2M x 4N); warp 64x32.
#define BM 128
#define BN 128
#define BK 32
#define PITCH2 20     // pitch in half2 units (16 data + 4 pad): frag loads conflict-free
__global__ __launch_bounds__(256) void gemm_tc_kernel(
    const float* __restrict__ A1, const __half* __restrict__ B1t,
    const float* __restrict__ A2, const __half* __restrict__ B2t,
    const float* __restrict__ bias, float* __restrict__ C,
    int relu, int dual)
{
    __shared__ uint32_t As2[BM * PITCH2];   // [row][k/2]
    __shared__ uint32_t Bs2[BN * PITCH2];   // [col][k/2]

    const int tid  = threadIdx.x;
    const int warp = tid >> 5;
    const int lane = tid & 31;
    const int wm = warp & 1;
    const int wn = warp >> 1;
    const int g  = lane >> 2;
    const int t  = lane & 3;
    const int bm = blockIdx.x * BM;
    const int bn = blockIdx.y * BN;

    float acc[4][4][4];
#pragma unroll
    for (int mt = 0; mt < 4; mt++)
#pragma unroll
        for (int nt = 0; nt < 4; nt++)
#pragma unroll
            for (int c = 0; c < 4; c++) acc[mt][nt][c] = 0.f;

    const int nPass = dual ? 2 : 1;
    for (int pass = 0; pass < nPass; ++pass) {
        const float* A  = pass ? A2 : A1;
        const __half* B = pass ? B2t : B1t;
        for (int k0 = 0; k0 < 256; k0 += BK) {
            __syncthreads();
            // A tile: 128 rows x 32 k. Each thread: 1 float4 -> 2 half2 (coalesced).
#pragma unroll
            for (int i = 0; i < 4; i++) {
                int idx = tid + i * 256;
                int m  = idx >> 3;
                int kq = (idx & 7) << 2;
                int gr = bm + m;
                float4 v = make_float4(0.f, 0.f, 0.f, 0.f);
                if (gr < NN)
                    v = *(const float4*)(A + (size_t)gr * 256 + k0 + kq);
                As2[m * PITCH2 + (kq >> 1)    ] = pack_h2(v.x, v.y);
                As2[m * PITCH2 + (kq >> 1) + 1] = pack_h2(v.z, v.w);
            }
            // B tile: fp16 pre-transposed [n][k]; one half2 per thread, p fastest
            // -> consecutive 4B within an n-row: coalesced.
#pragma unroll
            for (int i = 0; i < 8; i++) {
                int idx = tid + i * 256;      // 0..2047
                int n = idx >> 4;             // 0..127
                int p = idx & 15;             // k-pair
                Bs2[n * PITCH2 + p] =
                    *(const uint32_t*)(B + (size_t)(bn + n) * 256 + k0 + 2 * p);
            }
            __syncthreads();
#pragma unroll
            for (int kk = 0; kk < 2; kk++) {
                const int kk8 = kk * 8;
                uint32_t af[4][4];
#pragma unroll
                for (int mt = 0; mt < 4; mt++) {
                    int r0 = (wm * 64 + mt * 16 + g) * PITCH2;
                    int r8 = r0 + 8 * PITCH2;
                    af[mt][0] = As2[r0 + kk8 + t];
                    af[mt][1] = As2[r8 + kk8 + t];
                    af[mt][2] = As2[r0 + kk8 + t + 4];
                    af[mt][3] = As2[r8 + kk8 + t + 4];
                }
#pragma unroll
                for (int nt = 0; nt < 4; nt++) {
                    int cc = (wn * 32 + nt * 8 + g) * PITCH2;
                    uint32_t b0 = Bs2[cc + kk8 + t];
                    uint32_t b1 = Bs2[cc + kk8 + t + 4];
#pragma unroll
                    for (int mt = 0; mt < 4; mt++) {
                        asm volatile(
                            "mma.sync.aligned.m16n8k16.row.col.f32.f16.f16.f32 "
                            "{%0,%1,%2,%3}, {%4,%5,%6,%7}, {%8,%9}, {%0,%1,%2,%3};"
                            : "+f"(acc[mt][nt][0]), "+f"(acc[mt][nt][1]),
                              "+f"(acc[mt][nt][2]), "+f"(acc[mt][nt][3])
                            : "r"(af[mt][0]), "r"(af[mt][1]),
                              "r"(af[mt][2]), "r"(af[mt][3]),
                              "r"(b0), "r"(b1));
                    }
                }
            }
        }
    }

    // epilogue
#pragma unroll
    for (int nt = 0; nt < 4; nt++) {
        int col = bn + wn * 32 + nt * 8 + 2 * t;
        float bz0 = __ldg(&bias[col]);
        float bz1 = __ldg(&bias[col + 1]);
#pragma unroll
        for (int mt = 0; mt < 4; mt++) {
            int row0 = bm + wm * 64 + mt * 16 + g;
            float v0 = acc[mt][nt][0] + bz0;
            float v1 = acc[mt][nt][1] + bz1;
            float v2 = acc[mt][nt][2] + bz0;
            float v3 = acc[mt][nt][3] + bz1;
            if (relu) {
                v0 = fmaxf(v0, 0.f); v1 = fmaxf(v1, 0.f);
                v2 = fmaxf(v2, 0.f); v3 = fmaxf(v3, 0.f);
            }
            if (row0 < NN)
                *(float2*)(C + (size_t)row0 * 256 + col) = make_float2(v0, v1);
            if (row0 + 8 < NN)
                *(float2*)(C + (size_t)(row0 + 8) * 256 + col) = make_float2(v2, v3);
        }
    }
}

// ---------------- last layer projections + output init (exact fp32) ----
__global__ void node_post_kernel(const float* __restrict__ h,
                                 const float* __restrict__ rw3,
                                 const float* __restrict__ rb3,
                                 const float* __restrict__ sw3,
                                 float* __restrict__ out)
{
    int warp = (blockIdx.x * blockDim.x + threadIdx.x) >> 5;
    int lane = threadIdx.x & 31;
    if (warp >= NN) return;

    float pp[4] = {0.f, 0.f, 0.f, 0.f};
    float ss[4] = {0.f, 0.f, 0.f, 0.f};
#pragma unroll
    for (int j = 0; j < 8; j++) {
        int t = lane + 32 * j;
        float hv = h[(size_t)warp * HID + t];
#pragma unroll
        for (int c = 0; c < 4; c++) {
            pp[c] = fmaf(hv, __ldg(&rw3[t * 4 + c]), pp[c]);
            ss[c] = fmaf(hv, __ldg(&sw3[t * 4 + c]), ss[c]);
        }
    }
#pragma unroll
    for (int o = 16; o > 0; o >>= 1) {
#pragma unroll
        for (int c = 0; c < 4; c++) {
            pp[c] += __shfl_xor_sync(0xffffffffu, pp[c], o);
            ss[c] += __shfl_xor_sync(0xffffffffu, ss[c], o);
        }
    }
    if (lane == 0) {
        float cf = g_conf[warp];
        float om = 1.f - cf;
#pragma unroll
        for (int c = 0; c < 4; c++) {
            out[warp * 4 + c] = cf * g_weak[warp * 4 + c] + om * (ss[c] + __ldg(&rb3[c]));
            g_p3[warp * 4 + c] = pp[c];
        }
    }
}

// ---------------- final 4-wide edge scatter ----------------
__global__ void edge3_kernel(const int* __restrict__ src,
                             const int* __restrict__ tgt,
                             float* __restrict__ out)
{
    int e = blockIdx.x * blockDim.x + threadIdx.x;
    if (e >= NE) return;
    int s = __ldg(&src[e]);
    int t = __ldg(&tgt[e]);
    float om = 1.f - g_conf[t];
    float4 p = *(const float4*)&g_p3[s * 4];
    p.x *= om; p.y *= om; p.z *= om; p.w *= om;
    red_add_v4(&out[t * 4], p);
}

// ---------------- host ----------------
extern "C" void kernel_launch(void* const* d_in, const int* in_sizes, int n_in,
                              void* d_out, int out_size)
{
    const float* x   = (const float*)d_in[0];
    const int* ei    = (const int*)d_in[1];   // int32 (JAX x64 disabled)
    const float* w1  = (const float*)d_in[2];
    const float* b1  = (const float*)d_in[3];
    const float* w2  = (const float*)d_in[4];
    const float* b2  = (const float*)d_in[5];
    const float* e1  = (const float*)d_in[6];
    const float* be1 = (const float*)d_in[7];
    const float* e2  = (const float*)d_in[8];
    const float* be2 = (const float*)d_in[9];
    const float* RW[3] = {(const float*)d_in[10], (const float*)d_in[13], (const float*)d_in[16]};
    const float* RB[3] = {(const float*)d_in[11], (const float*)d_in[14], (const float*)d_in[17]};
    const float* SW[3] = {(const float*)d_in[12], (const float*)d_in[15], (const float*)d_in[18]};
    const float* rw3 = (const float*)d_in[19];
    const float* rb3 = (const float*)d_in[20];
    const float* sw3 = (const float*)d_in[21];
    float* out = (float*)d_out;

    float *buf0, *buf1, *agg;
    __half* wt;
    cudaGetSymbolAddress((void**)&buf0, g_buf0);
    cudaGetSymbolAddress((void**)&buf1, g_buf1);
    cudaGetSymbolAddress((void**)&agg,  g_agg);
    cudaGetSymbolAddress((void**)&wt,   g_wt);

    const int* src = ei;
    const int* tgt = ei + NE;

    // weight prep + node stage 1 (independent)
    wprep_kernel<<<(7 * 65536 + 255) / 256, 256>>>(e2, RW[0], SW[0], RW[1], SW[1], RW[2], SW[2]);
    node_pre_kernel<<<(NN * 32 + 255) / 256, 256>>>(x, w1, b1, w2, b2, e1, be1);

    dim3 gg((NN + BM - 1) / BM, 256 / BN);
    gemm_tc_kernel<<<gg, 256>>>(buf0, wt, nullptr, nullptr, be2, buf1, 0, 0);

    float* hcur = buf1;
    float* hnext = buf0;
    const int z4 = NN * (HID / 4);
    for (int l = 0; l < 3; l++) {
        zero_kernel<<<(z4 + 255) / 256, 256>>>((float4*)agg, z4);
        scatter_kernel<<<(NE * 32 + 255) / 256, 256>>>(hcur, agg, src, tgt);
        gemm_tc_kernel<<<gg, 256>>>(agg, wt + (1 + 2 * l) * 65536,
                                    hcur, wt + (2 + 2 * l) * 65536,
                                    RB[l], hnext, 1, 1);
        float* tmp = hcur; hcur = hnext; hnext = tmp;
    }

    node_post_kernel<<<(NN * 32 + 255) / 256, 256>>>(hcur, rw3, rb3, sw3, out);
    edge3_kernel<<<(NE + 255) / 256, 256>>>(src, tgt, out);
}

// round 11
// speedup vs baseline: 1.9892x; 1.3655x over previous
#include <cuda_runtime.h>
#include <cuda_fp16.h>
#include <cstdint>

#define NN 200000
#define NE 800000
#define HID 256
#define NSCAN (NN + 1)
#define SCAN_B 1024
#define NBLK ((NSCAN + SCAN_B - 1) / SCAN_B)   // 196

// ---------------- device scratch (no allocations allowed) ----------------
__device__ float g_buf0[(size_t)NN * HID];
__device__ float g_buf1[(size_t)NN * HID];
__device__ float g_agg [(size_t)NN * HID];
__device__ float g_weak[NN * 4];
__device__ float g_conf[NN];
__device__ float g_p3  [NN * 4];
__device__ __half g_wt[7 * 256 * 256];  // e2, rw0, sw0, rw1, sw1, rw2, sw2 as [n][k]
// CSR (target-sorted edges)
__device__ int g_off [NSCAN];
__device__ int g_pos [NN];
__device__ int g_esrc[NE];
__device__ int g_bsum[256];

__device__ __forceinline__ uint32_t pack_h2(float lo, float hi)
{
    __half2 h = __floats2half2_rn(lo, hi);
    return *(uint32_t*)&h;
}

// ================= CSR build =================
__global__ void zero_int_kernel(int* __restrict__ p, int n)
{
    int i = blockIdx.x * blockDim.x + threadIdx.x;
    if (i < n) p[i] = 0;
}

__global__ void hist_kernel(const int* __restrict__ tgt)
{
    int e = blockIdx.x * blockDim.x + threadIdx.x;
    if (e < NE) atomicAdd(&g_off[__ldg(&tgt[e]) + 1], 1);
}

__global__ void scan_block_kernel()
{
    __shared__ int sm[SCAN_B];
    int tid = threadIdx.x;
    int i = blockIdx.x * SCAN_B + tid;
    int v = (i < NSCAN) ? g_off[i] : 0;
    sm[tid] = v;
    __syncthreads();
#pragma unroll
    for (int off = 1; off < SCAN_B; off <<= 1) {
        int t = (tid >= off) ? sm[tid - off] : 0;
        __syncthreads();
        sm[tid] += t;
        __syncthreads();
    }
    if (i < NSCAN) g_off[i] = sm[tid];
    if (tid == SCAN_B - 1) g_bsum[blockIdx.x] = sm[tid];
}

__global__ void scan_tot_kernel()
{
    __shared__ int sm[256];
    int tid = threadIdx.x;
    int v = (tid < NBLK) ? g_bsum[tid] : 0;
    sm[tid] = v;
    __syncthreads();
#pragma unroll
    for (int off = 1; off < 256; off <<= 1) {
        int t = (tid >= off) ? sm[tid - off] : 0;
        __syncthreads();
        sm[tid] += t;
        __syncthreads();
    }
    if (tid < NBLK) g_bsum[tid] = sm[tid] - v;   // exclusive
}

__global__ void scan_add_kernel()
{
    int i = blockIdx.x * SCAN_B + threadIdx.x;
    if (i < NSCAN) g_off[i] += g_bsum[blockIdx.x];
}

__global__ void copy_pos_kernel()
{
    int i = blockIdx.x * blockDim.x + threadIdx.x;
    if (i < NN) g_pos[i] = g_off[i];
}

__global__ void fill_kernel(const int* __restrict__ src, const int* __restrict__ tgt)
{
    int e = blockIdx.x * blockDim.x + threadIdx.x;
    if (e >= NE) return;
    int p = atomicAdd(&g_pos[__ldg(&tgt[e])], 1);
    g_esrc[p] = __ldg(&src[e]);
}

// ================= gather: agg[t] = sum_{e: tgt=t} h[src[e]] =================
// warp per node, lane handles 8 contiguous floats
__global__ void gather_kernel(const float* __restrict__ h, float* __restrict__ agg)
{
    int gid  = blockIdx.x * blockDim.x + threadIdx.x;
    int node = gid >> 5;
    int lane = gid & 31;
    if (node >= NN) return;
    int beg = __ldg(&g_off[node]);
    int end = __ldg(&g_off[node + 1]);
    const int c = lane << 3;
    float4 a0 = make_float4(0.f, 0.f, 0.f, 0.f);
    float4 a1 = make_float4(0.f, 0.f, 0.f, 0.f);
    for (int e = beg; e < end; e++) {
        int s = __ldg(&g_esrc[e]);
        const float4* hp = (const float4*)(h + (size_t)s * HID + c);
        float4 v0 = __ldg(hp);
        float4 v1 = __ldg(hp + 1);
        a0.x += v0.x; a0.y += v0.y; a0.z += v0.z; a0.w += v0.w;
        a1.x += v1.x; a1.y += v1.y; a1.z += v1.z; a1.w += v1.w;
    }
    float4* dst = (float4*)(agg + (size_t)node * HID + c);
    dst[0] = a0;
    dst[1] = a1;
}

// ================= weight prep: transpose + fp16 =================
__global__ void wprep_kernel(const float* __restrict__ e2,
                             const float* __restrict__ rw0, const float* __restrict__ sw0,
                             const float* __restrict__ rw1, const float* __restrict__ sw1,
                             const float* __restrict__ rw2, const float* __restrict__ sw2)
{
    int idx = blockIdx.x * blockDim.x + threadIdx.x;
    if (idx >= 7 * 65536) return;
    int mat = idx >> 16;
    int r   = idx & 65535;
    int n   = r >> 8;
    int k   = r & 255;
    const float* W;
    switch (mat) {
        case 0: W = e2;  break;
        case 1: W = rw0; break;
        case 2: W = sw0; break;
        case 3: W = rw1; break;
        case 4: W = sw1; break;
        case 5: W = rw2; break;
        default: W = sw2; break;
    }
    g_wt[idx] = __float2half(__ldg(&W[k * 256 + n]));
}

// ---------------- node preprocessing: weak expert + conf + stage-1 of h --
__global__ void node_pre_kernel(const float* __restrict__ x,
                                const float* __restrict__ w1, const float* __restrict__ b1,
                                const float* __restrict__ w2, const float* __restrict__ b2,
                                const float* __restrict__ e1, const float* __restrict__ be1)
{
    int warp = (blockIdx.x * blockDim.x + threadIdx.x) >> 5;
    int lane = threadIdx.x & 31;
    if (warp >= NN) return;

    float xs[6];
#pragma unroll
    for (int i = 0; i < 6; i++) xs[i] = __ldg(&x[warp * 10 + 4 + i]);

    float pc0 = 0.f, pc1 = 0.f, pc2 = 0.f, pc3 = 0.f;
#pragma unroll
    for (int j = 0; j < 8; j++) {
        int t = lane + 32 * j;
        float ge = __ldg(&be1[t]);
        float gw = __ldg(&b1[t]);
#pragma unroll
        for (int i = 0; i < 6; i++) {
            ge = fmaf(xs[i], __ldg(&e1[i * HID + t]), ge);
            gw = fmaf(xs[i], __ldg(&w1[i * HID + t]), gw);
        }
        ge = fmaxf(ge, 0.f);
        gw = fmaxf(gw, 0.f);
        g_buf0[(size_t)warp * HID + t] = ge;
        pc0 = fmaf(gw, __ldg(&w2[t * 4 + 0]), pc0);
        pc1 = fmaf(gw, __ldg(&w2[t * 4 + 1]), pc1);
        pc2 = fmaf(gw, __ldg(&w2[t * 4 + 2]), pc2);
        pc3 = fmaf(gw, __ldg(&w2[t * 4 + 3]), pc3);
    }
#pragma unroll
    for (int o = 16; o > 0; o >>= 1) {
        pc0 += __shfl_xor_sync(0xffffffffu, pc0, o);
        pc1 += __shfl_xor_sync(0xffffffffu, pc1, o);
        pc2 += __shfl_xor_sync(0xffffffffu, pc2, o);
        pc3 += __shfl_xor_sync(0xffffffffu, pc3, o);
    }
    if (lane == 0) {
        float wk[4];
        wk[0] = pc0 + __ldg(&b2[0]);
        wk[1] = pc1 + __ldg(&b2[1]);
        wk[2] = pc2 + __ldg(&b2[2]);
        wk[3] = pc3 + __ldg(&b2[3]);
        float m = fmaxf(fmaxf(wk[0], wk[1]), fmaxf(wk[2], wk[3]));
        float ex[4], s = 0.f;
#pragma unroll
        for (int c = 0; c < 4; c++) { ex[c] = expf(wk[c] - m); s += ex[c]; }
        float inv = 1.f / s;
        float p[4], mean = 0.f;
#pragma unroll
        for (int c = 0; c < 4; c++) { p[c] = ex[c] * inv; mean += p[c]; }
        mean *= 0.25f;
        float var = 0.f, ent = 0.f;
#pragma unroll
        for (int c = 0; c < 4; c++) {
            float d = p[c] - mean;
            var += d * d;
            ent -= p[c] * logf(p[c] + 1e-8f);
        }
        var *= 0.25f;
        ent *= (1.f / 1.3862943611198906f);  // / log(4)
        float conf = 0.5f * (var + (1.f - ent));
        conf = fminf(fmaxf(conf, 0.f), 1.f);
        g_conf[warp] = conf;
#pragma unroll
        for (int c = 0; c < 4; c++) g_weak[warp * 4 + c] = wk[c];
    }
}

// ---------------- FP16 tensor-core GEMM (m16n8k16, fp32 accumulate) -------
#define BM 128
#define BN 128
#define BK 32
#define PITCH2 20
__global__ __launch_bounds__(256) void gemm_tc_kernel(
    const float* __restrict__ A1, const __half* __restrict__ B1t,
    const float* __restrict__ A2, const __half* __restrict__ B2t,
    const float* __restrict__ bias, float* __restrict__ C,
    int relu, int dual)
{
    __shared__ uint32_t As2[BM * PITCH2];
    __shared__ uint32_t Bs2[BN * PITCH2];

    const int tid  = threadIdx.x;
    const int warp = tid >> 5;
    const int lane = tid & 31;
    const int wm = warp & 1;
    const int wn = warp >> 1;
    const int g  = lane >> 2;
    const int t  = lane & 3;
    const int bm = blockIdx.x * BM;
    const int bn = blockIdx.y * BN;

    float acc[4][4][4];
#pragma unroll
    for (int mt = 0; mt < 4; mt++)
#pragma unroll
        for (int nt = 0; nt < 4; nt++)
#pragma unroll
            for (int c = 0; c < 4; c++) acc[mt][nt][c] = 0.f;

    const int nPass = dual ? 2 : 1;
    for (int pass = 0; pass < nPass; ++pass) {
        const float* A  = pass ? A2 : A1;
        const __half* B = pass ? B2t : B1t;
        for (int k0 = 0; k0 < 256; k0 += BK) {
            __syncthreads();
#pragma unroll
            for (int i = 0; i < 4; i++) {
                int idx = tid + i * 256;
                int m  = idx >> 3;
                int kq = (idx & 7) << 2;
                int gr = bm + m;
                float4 v = make_float4(0.f, 0.f, 0.f, 0.f);
                if (gr < NN)
                    v = *(const float4*)(A + (size_t)gr * 256 + k0 + kq);
                As2[m * PITCH2 + (kq >> 1)    ] = pack_h2(v.x, v.y);
                As2[m * PITCH2 + (kq >> 1) + 1] = pack_h2(v.z, v.w);
            }
#pragma unroll
            for (int i = 0; i < 8; i++) {
                int idx = tid + i * 256;
                int n = idx >> 4;
                int p = idx & 15;
                Bs2[n * PITCH2 + p] =
                    *(const uint32_t*)(B + (size_t)(bn + n) * 256 + k0 + 2 * p);
            }
            __syncthreads();
#pragma unroll
            for (int kk = 0; kk < 2; kk++) {
                const int kk8 = kk * 8;
                uint32_t af[4][4];
#pragma unroll
                for (int mt = 0; mt < 4; mt++) {
                    int r0 = (wm * 64 + mt * 16 + g) * PITCH2;
                    int r8 = r0 + 8 * PITCH2;
                    af[mt][0] = As2[r0 + kk8 + t];
                    af[mt][1] = As2[r8 + kk8 + t];
                    af[mt][2] = As2[r0 + kk8 + t + 4];
                    af[mt][3] = As2[r8 + kk8 + t + 4];
                }
#pragma unroll
                for (int nt = 0; nt < 4; nt++) {
                    int cc = (wn * 32 + nt * 8 + g) * PITCH2;
                    uint32_t b0 = Bs2[cc + kk8 + t];
                    uint32_t b1 = Bs2[cc + kk8 + t + 4];
#pragma unroll
                    for (int mt = 0; mt < 4; mt++) {
                        asm volatile(
                            "mma.sync.aligned.m16n8k16.row.col.f32.f16.f16.f32 "
                            "{%0,%1,%2,%3}, {%4,%5,%6,%7}, {%8,%9}, {%0,%1,%2,%3};"
                            : "+f"(acc[mt][nt][0]), "+f"(acc[mt][nt][1]),
                              "+f"(acc[mt][nt][2]), "+f"(acc[mt][nt][3])
                            : "r"(af[mt][0]), "r"(af[mt][1]),
                              "r"(af[mt][2]), "r"(af[mt][3]),
                              "r"(b0), "r"(b1));
                    }
                }
            }
        }
    }

#pragma unroll
    for (int nt = 0; nt < 4; nt++) {
        int col = bn + wn * 32 + nt * 8 + 2 * t;
        float bz0 = __ldg(&bias[col]);
        float bz1 = __ldg(&bias[col + 1]);
#pragma unroll
        for (int mt = 0; mt < 4; mt++) {
            int row0 = bm + wm * 64 + mt * 16 + g;
            float v0 = acc[mt][nt][0] + bz0;
            float v1 = acc[mt][nt][1] + bz1;
            float v2 = acc[mt][nt][2] + bz0;
            float v3 = acc[mt][nt][3] + bz1;
            if (relu) {
                v0 = fmaxf(v0, 0.f); v1 = fmaxf(v1, 0.f);
                v2 = fmaxf(v2, 0.f); v3 = fmaxf(v3, 0.f);
            }
            if (row0 < NN)
                *(float2*)(C + (size_t)row0 * 256 + col) = make_float2(v0, v1);
            if (row0 + 8 < NN)
                *(float2*)(C + (size_t)(row0 + 8) * 256 + col) = make_float2(v2, v3);
        }
    }
}

// ---------------- last layer projections + output init (exact fp32) ----
__global__ void node_post_kernel(const float* __restrict__ h,
                                 const float* __restrict__ rw3,
                                 const float* __restrict__ rb3,
                                 const float* __restrict__ sw3,
                                 float* __restrict__ out)
{
    int warp = (blockIdx.x * blockDim.x + threadIdx.x) >> 5;
    int lane = threadIdx.x & 31;
    if (warp >= NN) return;

    float pp[4] = {0.f, 0.f, 0.f, 0.f};
    float ss[4] = {0.f, 0.f, 0.f, 0.f};
#pragma unroll
    for (int j = 0; j < 8; j++) {
        int t = lane + 32 * j;
        float hv = h[(size_t)warp * HID + t];
#pragma unroll
        for (int c = 0; c < 4; c++) {
            pp[c] = fmaf(hv, __ldg(&rw3[t * 4 + c]), pp[c]);
            ss[c] = fmaf(hv, __ldg(&sw3[t * 4 + c]), ss[c]);
        }
    }
#pragma unroll
    for (int o = 16; o > 0; o >>= 1) {
#pragma unroll
        for (int c = 0; c < 4; c++) {
            pp[c] += __shfl_xor_sync(0xffffffffu, pp[c], o);
            ss[c] += __shfl_xor_sync(0xffffffffu, ss[c], o);
        }
    }
    if (lane == 0) {
        float cf = g_conf[warp];
        float om = 1.f - cf;
#pragma unroll
        for (int c = 0; c < 4; c++) {
            out[warp * 4 + c] = cf * g_weak[warp * 4 + c] + om * (ss[c] + __ldg(&rb3[c]));
            g_p3[warp * 4 + c] = pp[c];
        }
    }
}

// ---------------- final CSR gather: out[t] += (1-conf[t]) * sum p3[src] ----
__global__ void gather3_kernel(float* __restrict__ out)
{
    int t = blockIdx.x * blockDim.x + threadIdx.x;
    if (t >= NN) return;
    int beg = __ldg(&g_off[t]);
    int end = __ldg(&g_off[t + 1]);
    float4 s4 = make_float4(0.f, 0.f, 0.f, 0.f);
    for (int e = beg; e < end; e++) {
        int s = __ldg(&g_esrc[e]);
        float4 p = *(const float4*)&g_p3[s * 4];
        s4.x += p.x; s4.y += p.y; s4.z += p.z; s4.w += p.w;
    }
    float om = 1.f - g_conf[t];
    float4 o = *(float4*)&out[t * 4];
    o.x += om * s4.x; o.y += om * s4.y;
    o.z += om * s4.z; o.w += om * s4.w;
    *(float4*)&out[t * 4] = o;
}

// ---------------- host ----------------
extern "C" void kernel_launch(void* const* d_in, const int* in_sizes, int n_in,
                              void* d_out, int out_size)
{
    const float* x   = (const float*)d_in[0];
    const int* ei    = (const int*)d_in[1];   // int32 (JAX x64 disabled)
    const float* w1  = (const float*)d_in[2];
    const float* b1  = (const float*)d_in[3];
    const float* w2  = (const float*)d_in[4];
    const float* b2  = (const float*)d_in[5];
    const float* e1  = (const float*)d_in[6];
    const float* be1 = (const float*)d_in[7];
    const float* e2  = (const float*)d_in[8];
    const float* be2 = (const float*)d_in[9];
    const float* RW[3] = {(const float*)d_in[10], (const float*)d_in[13], (const float*)d_in[16]};
    const float* RB[3] = {(const float*)d_in[11], (const float*)d_in[14], (const float*)d_in[17]};
    const float* SW[3] = {(const float*)d_in[12], (const float*)d_in[15], (const float*)d_in[18]};
    const float* rw3 = (const float*)d_in[19];
    const float* rb3 = (const float*)d_in[20];
    const float* sw3 = (const float*)d_in[21];
    float* out = (float*)d_out;

    float *buf0, *buf1, *agg;
    __half* wt;
    int* offp;
    cudaGetSymbolAddress((void**)&buf0, g_buf0);
    cudaGetSymbolAddress((void**)&buf1, g_buf1);
    cudaGetSymbolAddress((void**)&agg,  g_agg);
    cudaGetSymbolAddress((void**)&wt,   g_wt);
    cudaGetSymbolAddress((void**)&offp, g_off);

    const int* src = ei;
    const int* tgt = ei + NE;

    // ---- CSR build (amortized over 3 gather layers + final gather) ----
    zero_int_kernel<<<(NSCAN + 255) / 256, 256>>>(offp, NSCAN);
    hist_kernel<<<(NE + 255) / 256, 256>>>(tgt);
    scan_block_kernel<<<NBLK, SCAN_B>>>();
    scan_tot_kernel<<<1, 256>>>();
    scan_add_kernel<<<NBLK, SCAN_B>>>();
    copy_pos_kernel<<<(NN + 255) / 256, 256>>>();
    fill_kernel<<<(NE + 255) / 256, 256>>>(src, tgt);

    // ---- weight prep + node stage 1 ----
    wprep_kernel<<<(7 * 65536 + 255) / 256, 256>>>(e2, RW[0], SW[0], RW[1], SW[1], RW[2], SW[2]);
    node_pre_kernel<<<(NN * 32 + 255) / 256, 256>>>(x, w1, b1, w2, b2, e1, be1);

    dim3 gg((NN + BM - 1) / BM, 256 / BN);
    gemm_tc_kernel<<<gg, 256>>>(buf0, wt, nullptr, nullptr, be2, buf1, 0, 0);

    float* hcur = buf1;
    float* hnext = buf0;
    for (int l = 0; l < 3; l++) {
        gather_kernel<<<(NN * 32 + 255) / 256, 256>>>(hcur, agg);
        gemm_tc_kernel<<<gg, 256>>>(agg, wt + (1 + 2 * l) * 65536,
                                    hcur, wt + (2 + 2 * l) * 65536,
                                    RB[l], hnext, 1, 1);
        float* tmp = hcur; hcur = hnext; hnext = tmp;
    }

    node_post_kernel<<<(NN * 32 + 255) / 256, 256>>>(hcur, rw3, rb3, sw3, out);
    gather3_kernel<<<(NN + 255) / 256, 256>>>(out);
}

// round 13
// speedup vs baseline: 2.4385x; 1.2258x over previous
// Resubmission of round-12 kernel (round-12 bench died to container infra, not kernel).
// fp16 activations end-to-end: halves GEMM A/C and gather traffic; removes
// cvt+pack from the issue-bound GEMM inner loop.
#include <cuda_runtime.h>
#include <cuda_fp16.h>
#include <cstdint>

#define NN 200000
#define NE 800000
#define HID 256
#define NSCAN (NN + 1)
#define SCAN_B 1024
#define NBLK ((NSCAN + SCAN_B - 1) / SCAN_B)   // 196

// ---------------- device scratch (no allocations allowed) ----------------
__device__ __half g_h0 [(size_t)NN * HID];   // activations, fp16
__device__ __half g_h1 [(size_t)NN * HID];
__device__ __half g_hag[(size_t)NN * HID];   // agg, fp16
__device__ float g_weak[NN * 4];
__device__ float g_conf[NN];
__device__ float g_p3  [NN * 4];
__device__ __half g_wt[7 * 256 * 256];  // e2, rw0, sw0, rw1, sw1, rw2, sw2 as [n][k]
// CSR (target-sorted edges)
__device__ int g_off [NSCAN];
__device__ int g_pos [NN];
__device__ int g_esrc[NE];
__device__ int g_bsum[256];

// ================= CSR build =================
__global__ void zero_int_kernel(int* __restrict__ p, int n)
{
    int i = blockIdx.x * blockDim.x + threadIdx.x;
    if (i < n) p[i] = 0;
}

__global__ void hist_kernel(const int* __restrict__ tgt)
{
    int e = blockIdx.x * blockDim.x + threadIdx.x;
    if (e < NE) atomicAdd(&g_off[__ldg(&tgt[e]) + 1], 1);
}

__global__ void scan_block_kernel()
{
    __shared__ int sm[SCAN_B];
    int tid = threadIdx.x;
    int i = blockIdx.x * SCAN_B + tid;
    int v = (i < NSCAN) ? g_off[i] : 0;
    sm[tid] = v;
    __syncthreads();
#pragma unroll
    for (int off = 1; off < SCAN_B; off <<= 1) {
        int t = (tid >= off) ? sm[tid - off] : 0;
        __syncthreads();
        sm[tid] += t;
        __syncthreads();
    }
    if (i < NSCAN) g_off[i] = sm[tid];
    if (tid == SCAN_B - 1) g_bsum[blockIdx.x] = sm[tid];
}

__global__ void scan_tot_kernel()
{
    __shared__ int sm[256];
    int tid = threadIdx.x;
    int v = (tid < NBLK) ? g_bsum[tid] : 0;
    sm[tid] = v;
    __syncthreads();
#pragma unroll
    for (int off = 1; off < 256; off <<= 1) {
        int t = (tid >= off) ? sm[tid - off] : 0;
        __syncthreads();
        sm[tid] += t;
        __syncthreads();
    }
    if (tid < NBLK) g_bsum[tid] = sm[tid] - v;   // exclusive
}

__global__ void scan_add_kernel()
{
    int i = blockIdx.x * SCAN_B + threadIdx.x;
    if (i < NSCAN) g_off[i] += g_bsum[blockIdx.x];
}

__global__ void copy_pos_kernel()
{
    int i = blockIdx.x * blockDim.x + threadIdx.x;
    if (i < NN) g_pos[i] = g_off[i];
}

__global__ void fill_kernel(const int* __restrict__ src, const int* __restrict__ tgt)
{
    int e = blockIdx.x * blockDim.x + threadIdx.x;
    if (e >= NE) return;
    int p = atomicAdd(&g_pos[__ldg(&tgt[e])], 1);
    g_esrc[p] = __ldg(&src[e]);
}

// ================= gather: agg[t] = sum_{e: tgt=t} h[src[e]], fp16 io =======
// warp per node, lane handles 8 contiguous halves (16B)
__global__ void gather_kernel(const __half* __restrict__ h, __half* __restrict__ agg)
{
    int gid  = blockIdx.x * blockDim.x + threadIdx.x;
    int node = gid >> 5;
    int lane = gid & 31;
    if (node >= NN) return;
    int beg = __ldg(&g_off[node]);
    int end = __ldg(&g_off[node + 1]);
    const int c = lane << 3;
    float acc[8];
#pragma unroll
    for (int i = 0; i < 8; i++) acc[i] = 0.f;
    for (int e = beg; e < end; e++) {
        int s = __ldg(&g_esrc[e]);
        uint4 v = __ldg((const uint4*)(h + (size_t)s * HID + c));
        const __half2* hp = (const __half2*)&v;
#pragma unroll
        for (int q = 0; q < 4; q++) {
            float2 f = __half22float2(hp[q]);
            acc[2 * q]     += f.x;
            acc[2 * q + 1] += f.y;
        }
    }
    uint4 o;
    __half2* op = (__half2*)&o;
#pragma unroll
    for (int q = 0; q < 4; q++)
        op[q] = __floats2half2_rn(acc[2 * q], acc[2 * q + 1]);
    *(uint4*)(agg + (size_t)node * HID + c) = o;
}

// ================= weight prep: transpose + fp16 =================
__global__ void wprep_kernel(const float* __restrict__ e2,
                             const float* __restrict__ rw0, const float* __restrict__ sw0,
                             const float* __restrict__ rw1, const float* __restrict__ sw1,
                             const float* __restrict__ rw2, const float* __restrict__ sw2)
{
    int idx = blockIdx.x * blockDim.x + threadIdx.x;
    if (idx >= 7 * 65536) return;
    int mat = idx >> 16;
    int r   = idx & 65535;
    int n   = r >> 8;
    int k   = r & 255;
    const float* W;
    switch (mat) {
        case 0: W = e2;  break;
        case 1: W = rw0; break;
        case 2: W = sw0; break;
        case 3: W = rw1; break;
        case 4: W = sw1; break;
        case 5: W = rw2; break;
        default: W = sw2; break;
    }
    g_wt[idx] = __float2half(__ldg(&W[k * 256 + n]));
}

// ---------------- node preprocessing: weak expert + conf + stage-1 of h --
__global__ void node_pre_kernel(const float* __restrict__ x,
                                const float* __restrict__ w1, const float* __restrict__ b1,
                                const float* __restrict__ w2, const float* __restrict__ b2,
                                const float* __restrict__ e1, const float* __restrict__ be1)
{
    int warp = (blockIdx.x * blockDim.x + threadIdx.x) >> 5;
    int lane = threadIdx.x & 31;
    if (warp >= NN) return;

    float xs[6];
#pragma unroll
    for (int i = 0; i < 6; i++) xs[i] = __ldg(&x[warp * 10 + 4 + i]);

    float pc0 = 0.f, pc1 = 0.f, pc2 = 0.f, pc3 = 0.f;
#pragma unroll
    for (int j = 0; j < 8; j++) {
        int t = lane + 32 * j;
        float ge = __ldg(&be1[t]);
        float gw = __ldg(&b1[t]);
#pragma unroll
        for (int i = 0; i < 6; i++) {
            ge = fmaf(xs[i], __ldg(&e1[i * HID + t]), ge);
            gw = fmaf(xs[i], __ldg(&w1[i * HID + t]), gw);
        }
        ge = fmaxf(ge, 0.f);
        gw = fmaxf(gw, 0.f);
        g_h0[(size_t)warp * HID + t] = __float2half(ge);
        pc0 = fmaf(gw, __ldg(&w2[t * 4 + 0]), pc0);
        pc1 = fmaf(gw, __ldg(&w2[t * 4 + 1]), pc1);
        pc2 = fmaf(gw, __ldg(&w2[t * 4 + 2]), pc2);
        pc3 = fmaf(gw, __ldg(&w2[t * 4 + 3]), pc3);
    }
#pragma unroll
    for (int o = 16; o > 0; o >>= 1) {
        pc0 += __shfl_xor_sync(0xffffffffu, pc0, o);
        pc1 += __shfl_xor_sync(0xffffffffu, pc1, o);
        pc2 += __shfl_xor_sync(0xffffffffu, pc2, o);
        pc3 += __shfl_xor_sync(0xffffffffu, pc3, o);
    }
    if (lane == 0) {
        float wk[4];
        wk[0] = pc0 + __ldg(&b2[0]);
        wk[1] = pc1 + __ldg(&b2[1]);
        wk[2] = pc2 + __ldg(&b2[2]);
        wk[3] = pc3 + __ldg(&b2[3]);
        float m = fmaxf(fmaxf(wk[0], wk[1]), fmaxf(wk[2], wk[3]));
        float ex[4], s = 0.f;
#pragma unroll
        for (int c = 0; c < 4; c++) { ex[c] = expf(wk[c] - m); s += ex[c]; }
        float inv = 1.f / s;
        float p[4], mean = 0.f;
#pragma unroll
        for (int c = 0; c < 4; c++) { p[c] = ex[c] * inv; mean += p[c]; }
        mean *= 0.25f;
        float var = 0.f, ent = 0.f;
#pragma unroll
        for (int c = 0; c < 4; c++) {
            float d = p[c] - mean;
            var += d * d;
            ent -= p[c] * logf(p[c] + 1e-8f);
        }
        var *= 0.25f;
        ent *= (1.f / 1.3862943611198906f);  // / log(4)
        float conf = 0.5f * (var + (1.f - ent));
        conf = fminf(fmaxf(conf, 0.f), 1.f);
        g_conf[warp] = conf;
#pragma unroll
        for (int c = 0; c < 4; c++) g_weak[warp * 4 + c] = wk[c];
    }
}

// ---------------- FP16 tensor-core GEMM (m16n8k16, fp32 accumulate) -------
// A fp16 [m][k], Bt fp16 [n][k], C fp16 out. Dual-pass accumulate.
#define BM 128
#define BN 128
#define BK 32
#define PITCH2 20
__global__ __launch_bounds__(256) void gemm_tc_kernel(
    const __half* __restrict__ A1, const __half* __restrict__ B1t,
    const __half* __restrict__ A2, const __half* __restrict__ B2t,
    const float* __restrict__ bias, __half* __restrict__ C,
    int relu, int dual)
{
    __shared__ uint32_t As2[BM * PITCH2];
    __shared__ uint32_t Bs2[BN * PITCH2];

    const int tid  = threadIdx.x;
    const int warp = tid >> 5;
    const int lane = tid & 31;
    const int wm = warp & 1;
    const int wn = warp >> 1;
    const int g  = lane >> 2;
    const int t  = lane & 3;
    const int bm = blockIdx.x * BM;
    const int bn = blockIdx.y * BN;

    float acc[4][4][4];
#pragma unroll
    for (int mt = 0; mt < 4; mt++)
#pragma unroll
        for (int nt = 0; nt < 4; nt++)
#pragma unroll
            for (int c = 0; c < 4; c++) acc[mt][nt][c] = 0.f;

    const int nPass = dual ? 2 : 1;
    for (int pass = 0; pass < nPass; ++pass) {
        const __half* A = pass ? A2 : A1;
        const __half* B = pass ? B2t : B1t;
        for (int k0 = 0; k0 < 256; k0 += BK) {
            __syncthreads();
            // A tile: 128 rows x 32 halves; each thread: one uint4 (8 halves).
#pragma unroll
            for (int i = 0; i < 2; i++) {
                int idx = tid + i * 256;      // 0..511
                int m  = idx >> 2;            // 0..127
                int kq = (idx & 3) << 3;      // 0,8,16,24 (halves)
                int gr = bm + m;
                uint4 v = make_uint4(0u, 0u, 0u, 0u);
                if (gr < NN)
                    v = *(const uint4*)(A + (size_t)gr * 256 + k0 + kq);
                uint32_t* d = &As2[m * PITCH2 + (kq >> 1)];
                d[0] = v.x; d[1] = v.y; d[2] = v.z; d[3] = v.w;
            }
            // B tile: [n][k] fp16; one half2 per thread (coalesced in k).
#pragma unroll
            for (int i = 0; i < 8; i++) {
                int idx = tid + i * 256;
                int n = idx >> 4;
                int p = idx & 15;
                Bs2[n * PITCH2 + p] =
                    *(const uint32_t*)(B + (size_t)(bn + n) * 256 + k0 + 2 * p);
            }
            __syncthreads();
#pragma unroll
            for (int kk = 0; kk < 2; kk++) {
                const int kk8 = kk * 8;
                uint32_t af[4][4];
#pragma unroll
                for (int mt = 0; mt < 4; mt++) {
                    int r0 = (wm * 64 + mt * 16 + g) * PITCH2;
                    int r8 = r0 + 8 * PITCH2;
                    af[mt][0] = As2[r0 + kk8 + t];
                    af[mt][1] = As2[r8 + kk8 + t];
                    af[mt][2] = As2[r0 + kk8 + t + 4];
                    af[mt][3] = As2[r8 + kk8 + t + 4];
                }
#pragma unroll
                for (int nt = 0; nt < 4; nt++) {
                    int cc = (wn * 32 + nt * 8 + g) * PITCH2;
                    uint32_t b0 = Bs2[cc + kk8 + t];
                    uint32_t b1 = Bs2[cc + kk8 + t + 4];
#pragma unroll
                    for (int mt = 0; mt < 4; mt++) {
                        asm volatile(
                            "mma.sync.aligned.m16n8k16.row.col.f32.f16.f16.f32 "
                            "{%0,%1,%2,%3}, {%4,%5,%6,%7}, {%8,%9}, {%0,%1,%2,%3};"
                            : "+f"(acc[mt][nt][0]), "+f"(acc[mt][nt][1]),
                              "+f"(acc[mt][nt][2]), "+f"(acc[mt][nt][3])
                            : "r"(af[mt][0]), "r"(af[mt][1]),
                              "r"(af[mt][2]), "r"(af[mt][3]),
                              "r"(b0), "r"(b1));
                    }
                }
            }
        }
    }

    // epilogue: write fp16 pairs
#pragma unroll
    for (int nt = 0; nt < 4; nt++) {
        int col = bn + wn * 32 + nt * 8 + 2 * t;
        float bz0 = __ldg(&bias[col]);
        float bz1 = __ldg(&bias[col + 1]);
#pragma unroll
        for (int mt = 0; mt < 4; mt++) {
            int row0 = bm + wm * 64 + mt * 16 + g;
            float v0 = acc[mt][nt][0] + bz0;
            float v1 = acc[mt][nt][1] + bz1;
            float v2 = acc[mt][nt][2] + bz0;
            float v3 = acc[mt][nt][3] + bz1;
            if (relu) {
                v0 = fmaxf(v0, 0.f); v1 = fmaxf(v1, 0.f);
                v2 = fmaxf(v2, 0.f); v3 = fmaxf(v3, 0.f);
            }
            if (row0 < NN)
                *(__half2*)(C + (size_t)row0 * 256 + col) = __floats2half2_rn(v0, v1);
            if (row0 + 8 < NN)
                *(__half2*)(C + (size_t)(row0 + 8) * 256 + col) = __floats2half2_rn(v2, v3);
        }
    }
}

// ---------------- last layer projections + output init (fp32 weights) ----
__global__ void node_post_kernel(const __half* __restrict__ h,
                                 const float* __restrict__ rw3,
                                 const float* __restrict__ rb3,
                                 const float* __restrict__ sw3,
                                 float* __restrict__ out)
{
    int warp = (blockIdx.x * blockDim.x + threadIdx.x) >> 5;
    int lane = threadIdx.x & 31;
    if (warp >= NN) return;

    float pp[4] = {0.f, 0.f, 0.f, 0.f};
    float ss[4] = {0.f, 0.f, 0.f, 0.f};
#pragma unroll
    for (int j = 0; j < 8; j++) {
        int t = lane + 32 * j;
        float hv = __half2float(h[(size_t)warp * HID + t]);
#pragma unroll
        for (int c = 0; c < 4; c++) {
            pp[c] = fmaf(hv, __ldg(&rw3[t * 4 + c]), pp[c]);
            ss[c] = fmaf(hv, __ldg(&sw3[t * 4 + c]), ss[c]);
        }
    }
#pragma unroll
    for (int o = 16; o > 0; o >>= 1) {
#pragma unroll
        for (int c = 0; c < 4; c++) {
            pp[c] += __shfl_xor_sync(0xffffffffu, pp[c], o);
            ss[c] += __shfl_xor_sync(0xffffffffu, ss[c], o);
        }
    }
    if (lane == 0) {
        float cf = g_conf[warp];
        float om = 1.f - cf;
#pragma unroll
        for (int c = 0; c < 4; c++) {
            out[warp * 4 + c] = cf * g_weak[warp * 4 + c] + om * (ss[c] + __ldg(&rb3[c]));
            g_p3[warp * 4 + c] = pp[c];
        }
    }
}

// ---------------- final CSR gather: out[t] += (1-conf[t]) * sum p3[src] ----
__global__ void gather3_kernel(float* __restrict__ out)
{
    int t = blockIdx.x * blockDim.x + threadIdx.x;
    if (t >= NN) return;
    int beg = __ldg(&g_off[t]);
    int end = __ldg(&g_off[t + 1]);
    float4 s4 = make_float4(0.f, 0.f, 0.f, 0.f);
    for (int e = beg; e < end; e++) {
        int s = __ldg(&g_esrc[e]);
        float4 p = *(const float4*)&g_p3[s * 4];
        s4.x += p.x; s4.y += p.y; s4.z += p.z; s4.w += p.w;
    }
    float om = 1.f - g_conf[t];
    float4 o = *(float4*)&out[t * 4];
    o.x += om * s4.x; o.y += om * s4.y;
    o.z += om * s4.z; o.w += om * s4.w;
    *(float4*)&out[t * 4] = o;
}

// ---------------- host ----------------
extern "C" void kernel_launch(void* const* d_in, const int* in_sizes, int n_in,
                              void* d_out, int out_size)
{
    const float* x   = (const float*)d_in[0];
    const int* ei    = (const int*)d_in[1];   // int32 (JAX x64 disabled)
    const float* w1  = (const float*)d_in[2];
    const float* b1  = (const float*)d_in[3];
    const float* w2  = (const float*)d_in[4];
    const float* b2  = (const float*)d_in[5];
    const float* e1  = (const float*)d_in[6];
    const float* be1 = (const float*)d_in[7];
    const float* e2  = (const float*)d_in[8];
    const float* be2 = (const float*)d_in[9];
    const float* RW[3] = {(const float*)d_in[10], (const float*)d_in[13], (const float*)d_in[16]};
    const float* RB[3] = {(const float*)d_in[11], (const float*)d_in[14], (const float*)d_in[17]};
    const float* SW[3] = {(const float*)d_in[12], (const float*)d_in[15], (const float*)d_in[18]};
    const float* rw3 = (const float*)d_in[19];
    const float* rb3 = (const float*)d_in[20];
    const float* sw3 = (const float*)d_in[21];
    float* out = (float*)d_out;

    __half *h0, *h1, *hag, *wt;
    int* offp;
    cudaGetSymbolAddress((void**)&h0,  g_h0);
    cudaGetSymbolAddress((void**)&h1,  g_h1);
    cudaGetSymbolAddress((void**)&hag, g_hag);
    cudaGetSymbolAddress((void**)&wt,  g_wt);
    cudaGetSymbolAddress((void**)&offp, g_off);

    const int* src = ei;
    const int* tgt = ei + NE;

    // ---- CSR build ----
    zero_int_kernel<<<(NSCAN + 255) / 256, 256>>>(offp, NSCAN);
    hist_kernel<<<(NE + 255) / 256, 256>>>(tgt);
    scan_block_kernel<<<NBLK, SCAN_B>>>();
    scan_tot_kernel<<<1, 256>>>();
    scan_add_kernel<<<NBLK, SCAN_B>>>();
    copy_pos_kernel<<<(NN + 255) / 256, 256>>>();
    fill_kernel<<<(NE + 255) / 256, 256>>>(src, tgt);

    // ---- weight prep + node stage 1 ----
    wprep_kernel<<<(7 * 65536 + 255) / 256, 256>>>(e2, RW[0], SW[0], RW[1], SW[1], RW[2], SW[2]);
    node_pre_kernel<<<(NN * 32 + 255) / 256, 256>>>(x, w1, b1, w2, b2, e1, be1);

    dim3 gg((NN + BM - 1) / BM, 256 / BN);
    gemm_tc_kernel<<<gg, 256>>>(h0, wt, nullptr, nullptr, be2, h1, 0, 0);

    __half* hcur = h1;
    __half* hnext = h0;
    for (int l = 0; l < 3; l++) {
        gather_kernel<<<(NN * 32 + 255) / 256, 256>>>(hcur, hag);
        gemm_tc_kernel<<<gg, 256>>>(hag, wt + (1 + 2 * l) * 65536,
                                    hcur, wt + (2 + 2 * l) * 65536,
                                    RB[l], hnext, 1, 1);
        __half* tmp = hcur; hcur = hnext; hnext = tmp;
    }

    node_post_kernel<<<(NN * 32 + 255) / 256, 256>>>(hcur, rw3, rb3, sw3, out);
    gather3_kernel<<<(NN + 255) / 256, 256>>>(out);
}

// round 15
// speedup vs baseline: 2.5221x; 1.0343x over previous
// Resubmission of round-14 kernel (round-14 bench died to container infra, not kernel).
// ldmatrix fragment loads replace 24 scalar LDS per warp-k16-step with 8 LDSM.
#include <cuda_runtime.h>
#include <cuda_fp16.h>
#include <cstdint>

#define NN 200000
#define NE 800000
#define HID 256
#define NSCAN (NN + 1)
#define SCAN_B 1024
#define NBLK ((NSCAN + SCAN_B - 1) / SCAN_B)   // 196

// ---------------- device scratch (no allocations allowed) ----------------
__device__ __half g_h0 [(size_t)NN * HID];   // activations, fp16
__device__ __half g_h1 [(size_t)NN * HID];
__device__ __half g_hag[(size_t)NN * HID];   // agg, fp16
__device__ float g_weak[NN * 4];
__device__ float g_conf[NN];
__device__ float g_p3  [NN * 4];
__device__ __half g_wt[7 * 256 * 256];  // e2, rw0, sw0, rw1, sw1, rw2, sw2 as [n][k]
// CSR (target-sorted edges)
__device__ int g_off [NSCAN];
__device__ int g_pos [NN];
__device__ int g_esrc[NE];
__device__ int g_bsum[256];

__device__ __forceinline__ uint32_t smem_u32(const void* p)
{
    uint32_t a;
    asm("{ .reg .u64 t; cvta.to.shared.u64 t, %1; cvt.u32.u64 %0, t; }"
        : "=r"(a) : "l"(p));
    return a;
}

// ================= CSR build =================
__global__ void zero_int_kernel(int* __restrict__ p, int n)
{
    int i = blockIdx.x * blockDim.x + threadIdx.x;
    if (i < n) p[i] = 0;
}

__global__ void hist_kernel(const int* __restrict__ tgt)
{
    int e = blockIdx.x * blockDim.x + threadIdx.x;
    if (e < NE) atomicAdd(&g_off[__ldg(&tgt[e]) + 1], 1);
}

__global__ void scan_block_kernel()
{
    __shared__ int sm[SCAN_B];
    int tid = threadIdx.x;
    int i = blockIdx.x * SCAN_B + tid;
    int v = (i < NSCAN) ? g_off[i] : 0;
    sm[tid] = v;
    __syncthreads();
#pragma unroll
    for (int off = 1; off < SCAN_B; off <<= 1) {
        int t = (tid >= off) ? sm[tid - off] : 0;
        __syncthreads();
        sm[tid] += t;
        __syncthreads();
    }
    if (i < NSCAN) g_off[i] = sm[tid];
    if (tid == SCAN_B - 1) g_bsum[blockIdx.x] = sm[tid];
}

__global__ void scan_tot_kernel()
{
    __shared__ int sm[256];
    int tid = threadIdx.x;
    int v = (tid < NBLK) ? g_bsum[tid] : 0;
    sm[tid] = v;
    __syncthreads();
#pragma unroll
    for (int off = 1; off < 256; off <<= 1) {
        int t = (tid >= off) ? sm[tid - off] : 0;
        __syncthreads();
        sm[tid] += t;
        __syncthreads();
    }
    if (tid < NBLK) g_bsum[tid] = sm[tid] - v;   // exclusive
}

__global__ void scan_add_kernel()
{
    int i = blockIdx.x * SCAN_B + threadIdx.x;
    if (i < NSCAN) g_off[i] += g_bsum[blockIdx.x];
}

__global__ void copy_pos_kernel()
{
    int i = blockIdx.x * blockDim.x + threadIdx.x;
    if (i < NN) g_pos[i] = g_off[i];
}

__global__ void fill_kernel(const int* __restrict__ src, const int* __restrict__ tgt)
{
    int e = blockIdx.x * blockDim.x + threadIdx.x;
    if (e >= NE) return;
    int p = atomicAdd(&g_pos[__ldg(&tgt[e])], 1);
    g_esrc[p] = __ldg(&src[e]);
}

// ================= gather: agg[t] = sum_{e: tgt=t} h[src[e]], fp16 io =======
__global__ void gather_kernel(const __half* __restrict__ h, __half* __restrict__ agg)
{
    int gid  = blockIdx.x * blockDim.x + threadIdx.x;
    int node = gid >> 5;
    int lane = gid & 31;
    if (node >= NN) return;
    int beg = __ldg(&g_off[node]);
    int end = __ldg(&g_off[node + 1]);
    const int c = lane << 3;
    float acc[8];
#pragma unroll
    for (int i = 0; i < 8; i++) acc[i] = 0.f;
    for (int e = beg; e < end; e++) {
        int s = __ldg(&g_esrc[e]);
        uint4 v = __ldg((const uint4*)(h + (size_t)s * HID + c));
        const __half2* hp = (const __half2*)&v;
#pragma unroll
        for (int q = 0; q < 4; q++) {
            float2 f = __half22float2(hp[q]);
            acc[2 * q]     += f.x;
            acc[2 * q + 1] += f.y;
        }
    }
    uint4 o;
    __half2* op = (__half2*)&o;
#pragma unroll
    for (int q = 0; q < 4; q++)
        op[q] = __floats2half2_rn(acc[2 * q], acc[2 * q + 1]);
    *(uint4*)(agg + (size_t)node * HID + c) = o;
}

// ================= weight prep: transpose + fp16 =================
__global__ void wprep_kernel(const float* __restrict__ e2,
                             const float* __restrict__ rw0, const float* __restrict__ sw0,
                             const float* __restrict__ rw1, const float* __restrict__ sw1,
                             const float* __restrict__ rw2, const float* __restrict__ sw2)
{
    int idx = blockIdx.x * blockDim.x + threadIdx.x;
    if (idx >= 7 * 65536) return;
    int mat = idx >> 16;
    int r   = idx & 65535;
    int n   = r >> 8;
    int k   = r & 255;
    const float* W;
    switch (mat) {
        case 0: W = e2;  break;
        case 1: W = rw0; break;
        case 2: W = sw0; break;
        case 3: W = rw1; break;
        case 4: W = sw1; break;
        case 5: W = rw2; break;
        default: W = sw2; break;
    }
    g_wt[idx] = __float2half(__ldg(&W[k * 256 + n]));
}

// ---------------- node preprocessing: weak expert + conf + stage-1 of h --
__global__ void node_pre_kernel(const float* __restrict__ x,
                                const float* __restrict__ w1, const float* __restrict__ b1,
                                const float* __restrict__ w2, const float* __restrict__ b2,
                                const float* __restrict__ e1, const float* __restrict__ be1)
{
    int warp = (blockIdx.x * blockDim.x + threadIdx.x) >> 5;
    int lane = threadIdx.x & 31;
    if (warp >= NN) return;

    float xs[6];
#pragma unroll
    for (int i = 0; i < 6; i++) xs[i] = __ldg(&x[warp * 10 + 4 + i]);

    float pc0 = 0.f, pc1 = 0.f, pc2 = 0.f, pc3 = 0.f;
#pragma unroll
    for (int j = 0; j < 8; j++) {
        int t = lane + 32 * j;
        float ge = __ldg(&be1[t]);
        float gw = __ldg(&b1[t]);
#pragma unroll
        for (int i = 0; i < 6; i++) {
            ge = fmaf(xs[i], __ldg(&e1[i * HID + t]), ge);
            gw = fmaf(xs[i], __ldg(&w1[i * HID + t]), gw);
        }
        ge = fmaxf(ge, 0.f);
        gw = fmaxf(gw, 0.f);
        g_h0[(size_t)warp * HID + t] = __float2half(ge);
        pc0 = fmaf(gw, __ldg(&w2[t * 4 + 0]), pc0);
        pc1 = fmaf(gw, __ldg(&w2[t * 4 + 1]), pc1);
        pc2 = fmaf(gw, __ldg(&w2[t * 4 + 2]), pc2);
        pc3 = fmaf(gw, __ldg(&w2[t * 4 + 3]), pc3);
    }
#pragma unroll
    for (int o = 16; o > 0; o >>= 1) {
        pc0 += __shfl_xor_sync(0xffffffffu, pc0, o);
        pc1 += __shfl_xor_sync(0xffffffffu, pc1, o);
        pc2 += __shfl_xor_sync(0xffffffffu, pc2, o);
        pc3 += __shfl_xor_sync(0xffffffffu, pc3, o);
    }
    if (lane == 0) {
        float wk[4];
        wk[0] = pc0 + __ldg(&b2[0]);
        wk[1] = pc1 + __ldg(&b2[1]);
        wk[2] = pc2 + __ldg(&b2[2]);
        wk[3] = pc3 + __ldg(&b2[3]);
        float m = fmaxf(fmaxf(wk[0], wk[1]), fmaxf(wk[2], wk[3]));
        float ex[4], s = 0.f;
#pragma unroll
        for (int c = 0; c < 4; c++) { ex[c] = expf(wk[c] - m); s += ex[c]; }
        float inv = 1.f / s;
        float p[4], mean = 0.f;
#pragma unroll
        for (int c = 0; c < 4; c++) { p[c] = ex[c] * inv; mean += p[c]; }
        mean *= 0.25f;
        float var = 0.f, ent = 0.f;
#pragma unroll
        for (int c = 0; c < 4; c++) {
            float d = p[c] - mean;
            var += d * d;
            ent -= p[c] * logf(p[c] + 1e-8f);
        }
        var *= 0.25f;
        ent *= (1.f / 1.3862943611198906f);  // / log(4)
        float conf = 0.5f * (var + (1.f - ent));
        conf = fminf(fmaxf(conf, 0.f), 1.f);
        g_conf[warp] = conf;
#pragma unroll
        for (int c = 0; c < 4; c++) g_weak[warp * 4 + c] = wk[c];
    }
}

// ---------------- FP16 tensor-core GEMM (m16n8k16 + ldmatrix) -------------
// A fp16 [m][k], Bt fp16 [n][k], C fp16 out. Dual-pass accumulate.
#define BM 128
#define BN 128
#define BK 32
#define PITCH2 20     // pitch in half2 units (16 data + 4 pad)
__global__ __launch_bounds__(256) void gemm_tc_kernel(
    const __half* __restrict__ A1, const __half* __restrict__ B1t,
    const __half* __restrict__ A2, const __half* __restrict__ B2t,
    const float* __restrict__ bias, __half* __restrict__ C,
    int relu, int dual)
{
    __shared__ uint32_t As2[BM * PITCH2];
    __shared__ uint32_t Bs2[BN * PITCH2];

    const int tid  = threadIdx.x;
    const int warp = tid >> 5;
    const int lane = tid & 31;
    const int wm = warp & 1;
    const int wn = warp >> 1;
    const int g  = lane >> 2;
    const int t  = lane & 3;
    const int bm = blockIdx.x * BM;
    const int bn = blockIdx.y * BN;

    // ldmatrix lane-address components
    const int lrow = lane & 7;          // row within 8x8 matrix
    const int lsel = (lane >> 3) & 1;   // A: matrices 1,3 -> +8 rows
    const int lk   = lane >> 4;         // A: matrices 2,3 -> +4 half2 in k
    // A base addr per mt tile (bytes in shared window)
    uint32_t aB[4];
#pragma unroll
    for (int mt = 0; mt < 4; mt++)
        aB[mt] = smem_u32(&As2[(wm * 64 + mt * 16 + lrow + lsel * 8) * PITCH2 + lk * 4]);
    // B base addr per nt tile: matrices 0,1 -> k +0/+4 half2 (lanes 8-15 select);
    // lanes 16-31 mirror lanes 0-15 (addresses unused but must be valid)
    const int bk = (lane >> 3) & 1;
    uint32_t bB[4];
#pragma unroll
    for (int nt = 0; nt < 4; nt++)
        bB[nt] = smem_u32(&Bs2[(wn * 32 + nt * 8 + lrow) * PITCH2 + bk * 4]);

    float acc[4][4][4];
#pragma unroll
    for (int mt = 0; mt < 4; mt++)
#pragma unroll
        for (int nt = 0; nt < 4; nt++)
#pragma unroll
            for (int c = 0; c < 4; c++) acc[mt][nt][c] = 0.f;

    const int nPass = dual ? 2 : 1;
    for (int pass = 0; pass < nPass; ++pass) {
        const __half* A = pass ? A2 : A1;
        const __half* B = pass ? B2t : B1t;
        for (int k0 = 0; k0 < 256; k0 += BK) {
            __syncthreads();
            // A tile: 128 rows x 32 halves; each thread: one uint4 (8 halves).
#pragma unroll
            for (int i = 0; i < 2; i++) {
                int idx = tid + i * 256;      // 0..511
                int m  = idx >> 2;            // 0..127
                int kq = (idx & 3) << 3;      // halves 0,8,16,24
                int gr = bm + m;
                uint4 v = make_uint4(0u, 0u, 0u, 0u);
                if (gr < NN)
                    v = *(const uint4*)(A + (size_t)gr * 256 + k0 + kq);
                uint32_t* d = &As2[m * PITCH2 + (kq >> 1)];
                d[0] = v.x; d[1] = v.y; d[2] = v.z; d[3] = v.w;
            }
            // B tile: [n][k] fp16; one uint4 (8 halves) per thread.
#pragma unroll
            for (int i = 0; i < 2; i++) {
                int idx = tid + i * 256;      // 0..511
                int n  = idx >> 2;            // 0..127
                int kq = (idx & 3) << 3;      // halves
                uint4 v = *(const uint4*)(B + (size_t)(bn + n) * 256 + k0 + kq);
                uint32_t* d = &Bs2[n * PITCH2 + (kq >> 1)];
                d[0] = v.x; d[1] = v.y; d[2] = v.z; d[3] = v.w;
            }
            __syncthreads();
#pragma unroll
            for (int kk = 0; kk < 2; kk++) {
                const uint32_t koff = kk * 32;   // 8 half2 = 32 bytes
                uint32_t af[4][4];
#pragma unroll
                for (int mt = 0; mt < 4; mt++) {
                    asm volatile(
                        "ldmatrix.sync.aligned.m8n8.x4.shared.b16 {%0,%1,%2,%3}, [%4];"
                        : "=r"(af[mt][0]), "=r"(af[mt][1]),
                          "=r"(af[mt][2]), "=r"(af[mt][3])
                        : "r"(aB[mt] + koff));
                }
#pragma unroll
                for (int nt = 0; nt < 4; nt++) {
                    uint32_t b0, b1;
                    asm volatile(
                        "ldmatrix.sync.aligned.m8n8.x2.shared.b16 {%0,%1}, [%2];"
                        : "=r"(b0), "=r"(b1)
                        : "r"(bB[nt] + koff));
#pragma unroll
                    for (int mt = 0; mt < 4; mt++) {
                        asm volatile(
                            "mma.sync.aligned.m16n8k16.row.col.f32.f16.f16.f32 "
                            "{%0,%1,%2,%3}, {%4,%5,%6,%7}, {%8,%9}, {%0,%1,%2,%3};"
                            : "+f"(acc[mt][nt][0]), "+f"(acc[mt][nt][1]),
                              "+f"(acc[mt][nt][2]), "+f"(acc[mt][nt][3])
                            : "r"(af[mt][0]), "r"(af[mt][1]),
                              "r"(af[mt][2]), "r"(af[mt][3]),
                              "r"(b0), "r"(b1));
                    }
                }
            }
        }
    }

    // epilogue: c0:(g,2t) c1:(g,2t+1) c2:(g+8,2t) c3:(g+8,2t+1)
#pragma unroll
    for (int nt = 0; nt < 4; nt++) {
        int col = bn + wn * 32 + nt * 8 + 2 * t;
        float bz0 = __ldg(&bias[col]);
        float bz1 = __ldg(&bias[col + 1]);
#pragma unroll
        for (int mt = 0; mt < 4; mt++) {
            int row0 = bm + wm * 64 + mt * 16 + g;
            float v0 = acc[mt][nt][0] + bz0;
            float v1 = acc[mt][nt][1] + bz1;
            float v2 = acc[mt][nt][2] + bz0;
            float v3 = acc[mt][nt][3] + bz1;
            if (relu) {
                v0 = fmaxf(v0, 0.f); v1 = fmaxf(v1, 0.f);
                v2 = fmaxf(v2, 0.f); v3 = fmaxf(v3, 0.f);
            }
            if (row0 < NN)
                *(__half2*)(C + (size_t)row0 * 256 + col) = __floats2half2_rn(v0, v1);
            if (row0 + 8 < NN)
                *(__half2*)(C + (size_t)(row0 + 8) * 256 + col) = __floats2half2_rn(v2, v3);
        }
    }
}

// ---------------- last layer projections + output init (fp32 weights) ----
__global__ void node_post_kernel(const __half* __restrict__ h,
                                 const float* __restrict__ rw3,
                                 const float* __restrict__ rb3,
                                 const float* __restrict__ sw3,
                                 float* __restrict__ out)
{
    int warp = (blockIdx.x * blockDim.x + threadIdx.x) >> 5;
    int lane = threadIdx.x & 31;
    if (warp >= NN) return;

    float pp[4] = {0.f, 0.f, 0.f, 0.f};
    float ss[4] = {0.f, 0.f, 0.f, 0.f};
#pragma unroll
    for (int j = 0; j < 8; j++) {
        int t = lane + 32 * j;
        float hv = __half2float(h[(size_t)warp * HID + t]);
#pragma unroll
        for (int c = 0; c < 4; c++) {
            pp[c] = fmaf(hv, __ldg(&rw3[t * 4 + c]), pp[c]);
            ss[c] = fmaf(hv, __ldg(&sw3[t * 4 + c]), ss[c]);
        }
    }
#pragma unroll
    for (int o = 16; o > 0; o >>= 1) {
#pragma unroll
        for (int c = 0; c < 4; c++) {
            pp[c] += __shfl_xor_sync(0xffffffffu, pp[c], o);
            ss[c] += __shfl_xor_sync(0xffffffffu, ss[c], o);
        }
    }
    if (lane == 0) {
        float cf = g_conf[warp];
        float om = 1.f - cf;
#pragma unroll
        for (int c = 0; c < 4; c++) {
            out[warp * 4 + c] = cf * g_weak[warp * 4 + c] + om * (ss[c] + __ldg(&rb3[c]));
            g_p3[warp * 4 + c] = pp[c];
        }
    }
}

// ---------------- final CSR gather: out[t] += (1-conf[t]) * sum p3[src] ----
__global__ void gather3_kernel(float* __restrict__ out)
{
    int t = blockIdx.x * blockDim.x + threadIdx.x;
    if (t >= NN) return;
    int beg = __ldg(&g_off[t]);
    int end = __ldg(&g_off[t + 1]);
    float4 s4 = make_float4(0.f, 0.f, 0.f, 0.f);
    for (int e = beg; e < end; e++) {
        int s = __ldg(&g_esrc[e]);
        float4 p = *(const float4*)&g_p3[s * 4];
        s4.x += p.x; s4.y += p.y; s4.z += p.z; s4.w += p.w;
    }
    float om = 1.f - g_conf[t];
    float4 o = *(float4*)&out[t * 4];
    o.x += om * s4.x; o.y += om * s4.y;
    o.z += om * s4.z; o.w += om * s4.w;
    *(float4*)&out[t * 4] = o;
}

// ---------------- host ----------------
extern "C" void kernel_launch(void* const* d_in, const int* in_sizes, int n_in,
                              void* d_out, int out_size)
{
    const float* x   = (const float*)d_in[0];
    const int* ei    = (const int*)d_in[1];   // int32 (JAX x64 disabled)
    const float* w1  = (const float*)d_in[2];
    const float* b1  = (const float*)d_in[3];
    const float* w2  = (const float*)d_in[4];
    const float* b2  = (const float*)d_in[5];
    const float* e1  = (const float*)d_in[6];
    const float* be1 = (const float*)d_in[7];
    const float* e2  = (const float*)d_in[8];
    const float* be2 = (const float*)d_in[9];
    const float* RW[3] = {(const float*)d_in[10], (const float*)d_in[13], (const float*)d_in[16]};
    const float* RB[3] = {(const float*)d_in[11], (const float*)d_in[14], (const float*)d_in[17]};
    const float* SW[3] = {(const float*)d_in[12], (const float*)d_in[15], (const float*)d_in[18]};
    const float* rw3 = (const float*)d_in[19];
    const float* rb3 = (const float*)d_in[20];
    const float* sw3 = (const float*)d_in[21];
    float* out = (float*)d_out;

    __half *h0, *h1, *hag, *wt;
    int* offp;
    cudaGetSymbolAddress((void**)&h0,  g_h0);
    cudaGetSymbolAddress((void**)&h1,  g_h1);
    cudaGetSymbolAddress((void**)&hag, g_hag);
    cudaGetSymbolAddress((void**)&wt,  g_wt);
    cudaGetSymbolAddress((void**)&offp, g_off);

    const int* src = ei;
    const int* tgt = ei + NE;

    // ---- CSR build ----
    zero_int_kernel<<<(NSCAN + 255) / 256, 256>>>(offp, NSCAN);
    hist_kernel<<<(NE + 255) / 256, 256>>>(tgt);
    scan_block_kernel<<<NBLK, SCAN_B>>>();
    scan_tot_kernel<<<1, 256>>>();
    scan_add_kernel<<<NBLK, SCAN_B>>>();
    copy_pos_kernel<<<(NN + 255) / 256, 256>>>();
    fill_kernel<<<(NE + 255) / 256, 256>>>(src, tgt);

    // ---- weight prep + node stage 1 ----
    wprep_kernel<<<(7 * 65536 + 255) / 256, 256>>>(e2, RW[0], SW[0], RW[1], SW[1], RW[2], SW[2]);
    node_pre_kernel<<<(NN * 32 + 255) / 256, 256>>>(x, w1, b1, w2, b2, e1, be1);

    dim3 gg((NN + BM - 1) / BM, 256 / BN);
    gemm_tc_kernel<<<gg, 256>>>(h0, wt, nullptr, nullptr, be2, h1, 0, 0);

    __half* hcur = h1;
    __half* hnext = h0;
    for (int l = 0; l < 3; l++) {
        gather_kernel<<<(NN * 32 + 255) / 256, 256>>>(hcur, hag);
        gemm_tc_kernel<<<gg, 256>>>(hag, wt + (1 + 2 * l) * 65536,
                                    hcur, wt + (2 + 2 * l) * 65536,
                                    RB[l], hnext, 1, 1);
        __half* tmp = hcur; hcur = hnext; hnext = tmp;
    }

    node_post_kernel<<<(NN * 32 + 255) / 256, 256>>>(hcur, rw3, rb3, sw3, out);
    gather3_kernel<<<(NN + 255) / 256, 256>>>(out);
}

// round 17
// speedup vs baseline: 2.7773x; 1.1012x over previous
// Resubmission of round-16 kernel (container infra failure, no kernel signal).
// Change vs R16: __align__(16) on smem tile buffers (cp.async 16B dst alignment).
#include <cuda_runtime.h>
#include <cuda_fp16.h>
#include <cstdint>

#define NN 200000
#define NE 800000
#define HID 256
#define NSCAN (NN + 1)
#define SCAN_B 1024
#define NBLK ((NSCAN + SCAN_B - 1) / SCAN_B)   // 196

// ---------------- device scratch (no allocations allowed) ----------------
__device__ __half g_h0 [(size_t)NN * HID];   // activations, fp16
__device__ __half g_h1 [(size_t)NN * HID];
__device__ __half g_hag[(size_t)NN * HID];   // agg, fp16
__device__ float g_weak[NN * 4];
__device__ float g_conf[NN];
__device__ float g_p3  [NN * 4];
__device__ __half g_wt[7 * 256 * 256];  // e2, rw0, sw0, rw1, sw1, rw2, sw2 as [n][k]
// CSR (target-sorted edges)
__device__ int g_off [NSCAN];
__device__ int g_pos [NN];
__device__ int g_esrc[NE];
__device__ int g_bsum[256];

__device__ __forceinline__ uint32_t smem_u32(const void* p)
{
    uint32_t a;
    asm("{ .reg .u64 t; cvta.to.shared.u64 t, %1; cvt.u32.u64 %0, t; }"
        : "=r"(a) : "l"(p));
    return a;
}

// ================= CSR build =================
__global__ void zero_int_kernel(int* __restrict__ p, int n)
{
    int i = blockIdx.x * blockDim.x + threadIdx.x;
    if (i < n) p[i] = 0;
}

__global__ void hist_kernel(const int* __restrict__ tgt)
{
    int e = blockIdx.x * blockDim.x + threadIdx.x;
    if (e < NE) atomicAdd(&g_off[__ldg(&tgt[e]) + 1], 1);
}

__global__ void scan_block_kernel()
{
    __shared__ int sm[SCAN_B];
    int tid = threadIdx.x;
    int i = blockIdx.x * SCAN_B + tid;
    int v = (i < NSCAN) ? g_off[i] : 0;
    sm[tid] = v;
    __syncthreads();
#pragma unroll
    for (int off = 1; off < SCAN_B; off <<= 1) {
        int t = (tid >= off) ? sm[tid - off] : 0;
        __syncthreads();
        sm[tid] += t;
        __syncthreads();
    }
    if (i < NSCAN) g_off[i] = sm[tid];
    if (tid == SCAN_B - 1) g_bsum[blockIdx.x] = sm[tid];
}

__global__ void scan_tot_kernel()
{
    __shared__ int sm[256];
    int tid = threadIdx.x;
    int v = (tid < NBLK) ? g_bsum[tid] : 0;
    sm[tid] = v;
    __syncthreads();
#pragma unroll
    for (int off = 1; off < 256; off <<= 1) {
        int t = (tid >= off) ? sm[tid - off] : 0;
        __syncthreads();
        sm[tid] += t;
        __syncthreads();
    }
    if (tid < NBLK) g_bsum[tid] = sm[tid] - v;   // exclusive
}

// scan_add + copy_pos fused
__global__ void scan_add_kernel()
{
    int i = blockIdx.x * SCAN_B + threadIdx.x;
    if (i < NSCAN) {
        int v = g_off[i] + g_bsum[blockIdx.x];
        g_off[i] = v;
        if (i < NN) g_pos[i] = v;
    }
}

__global__ void fill_kernel(const int* __restrict__ src, const int* __restrict__ tgt)
{
    int e = blockIdx.x * blockDim.x + threadIdx.x;
    if (e >= NE) return;
    int p = atomicAdd(&g_pos[__ldg(&tgt[e])], 1);
    g_esrc[p] = __ldg(&src[e]);
}

// ================= gather: agg[t] = sum_{e: tgt=t} h[src[e]], fp16 io =======
__global__ void gather_kernel(const __half* __restrict__ h, __half* __restrict__ agg)
{
    int gid  = blockIdx.x * blockDim.x + threadIdx.x;
    int node = gid >> 5;
    int lane = gid & 31;
    if (node >= NN) return;
    int beg = __ldg(&g_off[node]);
    int end = __ldg(&g_off[node + 1]);
    const int c = lane << 3;
    float acc[8];
#pragma unroll
    for (int i = 0; i < 8; i++) acc[i] = 0.f;
    for (int e = beg; e < end; e++) {
        int s = __ldg(&g_esrc[e]);
        uint4 v = __ldg((const uint4*)(h + (size_t)s * HID + c));
        const __half2* hp = (const __half2*)&v;
#pragma unroll
        for (int q = 0; q < 4; q++) {
            float2 f = __half22float2(hp[q]);
            acc[2 * q]     += f.x;
            acc[2 * q + 1] += f.y;
        }
    }
    uint4 o;
    __half2* op = (__half2*)&o;
#pragma unroll
    for (int q = 0; q < 4; q++)
        op[q] = __floats2half2_rn(acc[2 * q], acc[2 * q + 1]);
    *(uint4*)(agg + (size_t)node * HID + c) = o;
}

// ================= weight prep: transpose + fp16 =================
__global__ void wprep_kernel(const float* __restrict__ e2,
                             const float* __restrict__ rw0, const float* __restrict__ sw0,
                             const float* __restrict__ rw1, const float* __restrict__ sw1,
                             const float* __restrict__ rw2, const float* __restrict__ sw2)
{
    int idx = blockIdx.x * blockDim.x + threadIdx.x;
    if (idx >= 7 * 65536) return;
    int mat = idx >> 16;
    int r   = idx & 65535;
    int n   = r >> 8;
    int k   = r & 255;
    const float* W;
    switch (mat) {
        case 0: W = e2;  break;
        case 1: W = rw0; break;
        case 2: W = sw0; break;
        case 3: W = rw1; break;
        case 4: W = sw1; break;
        case 5: W = rw2; break;
        default: W = sw2; break;
    }
    g_wt[idx] = __float2half(__ldg(&W[k * 256 + n]));
}

// ---------------- node preprocessing: weak expert + conf + stage-1 of h --
__global__ void node_pre_kernel(const float* __restrict__ x,
                                const float* __restrict__ w1, const float* __restrict__ b1,
                                const float* __restrict__ w2, const float* __restrict__ b2,
                                const float* __restrict__ e1, const float* __restrict__ be1)
{
    int warp = (blockIdx.x * blockDim.x + threadIdx.x) >> 5;
    int lane = threadIdx.x & 31;
    if (warp >= NN) return;

    float xs[6];
#pragma unroll
    for (int i = 0; i < 6; i++) xs[i] = __ldg(&x[warp * 10 + 4 + i]);

    float pc0 = 0.f, pc1 = 0.f, pc2 = 0.f, pc3 = 0.f;
#pragma unroll
    for (int j = 0; j < 8; j++) {
        int t = lane + 32 * j;
        float ge = __ldg(&be1[t]);
        float gw = __ldg(&b1[t]);
#pragma unroll
        for (int i = 0; i < 6; i++) {
            ge = fmaf(xs[i], __ldg(&e1[i * HID + t]), ge);
            gw = fmaf(xs[i], __ldg(&w1[i * HID + t]), gw);
        }
        ge = fmaxf(ge, 0.f);
        gw = fmaxf(gw, 0.f);
        g_h0[(size_t)warp * HID + t] = __float2half(ge);
        pc0 = fmaf(gw, __ldg(&w2[t * 4 + 0]), pc0);
        pc1 = fmaf(gw, __ldg(&w2[t * 4 + 1]), pc1);
        pc2 = fmaf(gw, __ldg(&w2[t * 4 + 2]), pc2);
        pc3 = fmaf(gw, __ldg(&w2[t * 4 + 3]), pc3);
    }
#pragma unroll
    for (int o = 16; o > 0; o >>= 1) {
        pc0 += __shfl_xor_sync(0xffffffffu, pc0, o);
        pc1 += __shfl_xor_sync(0xffffffffu, pc1, o);
        pc2 += __shfl_xor_sync(0xffffffffu, pc2, o);
        pc3 += __shfl_xor_sync(0xffffffffu, pc3, o);
    }
    if (lane == 0) {
        float wk[4];
        wk[0] = pc0 + __ldg(&b2[0]);
        wk[1] = pc1 + __ldg(&b2[1]);
        wk[2] = pc2 + __ldg(&b2[2]);
        wk[3] = pc3 + __ldg(&b2[3]);
        float m = fmaxf(fmaxf(wk[0], wk[1]), fmaxf(wk[2], wk[3]));
        float ex[4], s = 0.f;
#pragma unroll
        for (int c = 0; c < 4; c++) { ex[c] = expf(wk[c] - m); s += ex[c]; }
        float inv = 1.f / s;
        float p[4], mean = 0.f;
#pragma unroll
        for (int c = 0; c < 4; c++) { p[c] = ex[c] * inv; mean += p[c]; }
        mean *= 0.25f;
        float var = 0.f, ent = 0.f;
#pragma unroll
        for (int c = 0; c < 4; c++) {
            float d = p[c] - mean;
            var += d * d;
            ent -= p[c] * logf(p[c] + 1e-8f);
        }
        var *= 0.25f;
        ent *= (1.f / 1.3862943611198906f);  // / log(4)
        float conf = 0.5f * (var + (1.f - ent));
        conf = fminf(fmaxf(conf, 0.f), 1.f);
        g_conf[warp] = conf;
#pragma unroll
        for (int c = 0; c < 4; c++) g_weak[warp * 4 + c] = wk[c];
    }
}

// ---------------- FP16 tensor-core GEMM (m16n8k16 + ldmatrix + cp.async) --
// A fp16 [m][k], Bt fp16 [n][k], C fp16 out. Dual-pass accumulate.
// Two-stage cp.async pipeline: chunk c+1 loads overlap chunk c compute.
#define BM 128
#define BN 128
#define BK 32
#define PITCH2 20     // pitch in half2 units (16 data + 4 pad)
__global__ __launch_bounds__(256) void gemm_tc_kernel(
    const __half* __restrict__ A1, const __half* __restrict__ B1t,
    const __half* __restrict__ A2, const __half* __restrict__ B2t,
    const float* __restrict__ bias, __half* __restrict__ C,
    int relu, int dual)
{
    __shared__ __align__(16) uint32_t As2[2][BM * PITCH2];
    __shared__ __align__(16) uint32_t Bs2[2][BN * PITCH2];

    const int tid  = threadIdx.x;
    const int warp = tid >> 5;
    const int lane = tid & 31;
    const int wm = warp & 1;
    const int wn = warp >> 1;
    const int g  = lane >> 2;
    const int t  = lane & 3;
    const int bm = blockIdx.x * BM;
    const int bn = blockIdx.y * BN;

    // ---- per-thread load coordinates (2 x 16B cp.async each for A and B) --
    const int am  = tid >> 2;             // rows am and am+64
    const int akq = (tid & 3) << 3;       // halves 0,8,16,24
    uint32_t aD[2][2], bD[2][2];
#pragma unroll
    for (int s = 0; s < 2; s++) {
        aD[s][0] = smem_u32(&As2[s][am * PITCH2 + (akq >> 1)]);
        aD[s][1] = smem_u32(&As2[s][(am + 64) * PITCH2 + (akq >> 1)]);
        bD[s][0] = smem_u32(&Bs2[s][am * PITCH2 + (akq >> 1)]);
        bD[s][1] = smem_u32(&Bs2[s][(am + 64) * PITCH2 + (akq >> 1)]);
    }

    // ---- ldmatrix lane addresses per buffer --------------------------------
    const int lrow = lane & 7;
    const int lsel = (lane >> 3) & 1;
    const int lk   = lane >> 4;
    const int bk   = (lane >> 3) & 1;
    uint32_t aB[2][4], bB[2][4];
#pragma unroll
    for (int s = 0; s < 2; s++) {
#pragma unroll
        for (int mt = 0; mt < 4; mt++)
            aB[s][mt] = smem_u32(&As2[s][(wm * 64 + mt * 16 + lrow + lsel * 8) * PITCH2 + lk * 4]);
#pragma unroll
        for (int nt = 0; nt < 4; nt++)
            bB[s][nt] = smem_u32(&Bs2[s][(wn * 32 + nt * 8 + lrow) * PITCH2 + bk * 4]);
    }

    float acc[4][4][4];
#pragma unroll
    for (int mt = 0; mt < 4; mt++)
#pragma unroll
        for (int nt = 0; nt < 4; nt++)
#pragma unroll
            for (int c = 0; c < 4; c++) acc[mt][nt][c] = 0.f;

    const int nChunk = dual ? 16 : 8;

    // issue cp.async loads for chunk ch into buffer s
#define LOAD_CHUNK(ch, s)                                                      \
    {                                                                          \
        const __half* A = ((ch) >= 8) ? A2 : A1;                               \
        const __half* B = ((ch) >= 8) ? B2t : B1t;                             \
        int k0 = ((ch) & 7) * BK;                                              \
        int gr0 = bm + am, gr1 = bm + am + 64;                                 \
        int p0 = (gr0 < NN) ? 16 : 0;                                          \
        int p1 = (gr1 < NN) ? 16 : 0;                                          \
        asm volatile("cp.async.ca.shared.global [%0], [%1], 16, %2;"           \
                     :: "r"(aD[s][0]), "l"(A + (size_t)gr0 * 256 + k0 + akq),  \
                        "r"(p0));                                              \
        asm volatile("cp.async.ca.shared.global [%0], [%1], 16, %2;"           \
                     :: "r"(aD[s][1]), "l"(A + (size_t)gr1 * 256 + k0 + akq),  \
                        "r"(p1));                                              \
        asm volatile("cp.async.ca.shared.global [%0], [%1], 16;"               \
                     :: "r"(bD[s][0]), "l"(B + (size_t)(bn + am) * 256 + k0 + akq)); \
        asm volatile("cp.async.ca.shared.global [%0], [%1], 16;"               \
                     :: "r"(bD[s][1]), "l"(B + (size_t)(bn + am + 64) * 256 + k0 + akq)); \
        asm volatile("cp.async.commit_group;");                                \
    }

    LOAD_CHUNK(0, 0);

    for (int c = 0; c < nChunk; ++c) {
        const int b = c & 1;
        if (c + 1 < nChunk) {
            LOAD_CHUNK(c + 1, b ^ 1);
            asm volatile("cp.async.wait_group 1;");
        } else {
            asm volatile("cp.async.wait_group 0;");
        }
        __syncthreads();
#pragma unroll
        for (int kk = 0; kk < 2; kk++) {
            const uint32_t koff = kk * 32;   // 8 half2 = 32 bytes
            uint32_t af[4][4];
#pragma unroll
            for (int mt = 0; mt < 4; mt++) {
                asm volatile(
                    "ldmatrix.sync.aligned.m8n8.x4.shared.b16 {%0,%1,%2,%3}, [%4];"
                    : "=r"(af[mt][0]), "=r"(af[mt][1]),
                      "=r"(af[mt][2]), "=r"(af[mt][3])
                    : "r"(aB[b][mt] + koff));
            }
#pragma unroll
            for (int nt = 0; nt < 4; nt++) {
                uint32_t b0, b1;
                asm volatile(
                    "ldmatrix.sync.aligned.m8n8.x2.shared.b16 {%0,%1}, [%2];"
                    : "=r"(b0), "=r"(b1)
                    : "r"(bB[b][nt] + koff));
#pragma unroll
                for (int mt = 0; mt < 4; mt++) {
                    asm volatile(
                        "mma.sync.aligned.m16n8k16.row.col.f32.f16.f16.f32 "
                        "{%0,%1,%2,%3}, {%4,%5,%6,%7}, {%8,%9}, {%0,%1,%2,%3};"
                        : "+f"(acc[mt][nt][0]), "+f"(acc[mt][nt][1]),
                          "+f"(acc[mt][nt][2]), "+f"(acc[mt][nt][3])
                        : "r"(af[mt][0]), "r"(af[mt][1]),
                          "r"(af[mt][2]), "r"(af[mt][3]),
                        "r"(b0), "r"(b1));
                }
            }
        }
        __syncthreads();
    }
#undef LOAD_CHUNK

    // epilogue: c0:(g,2t) c1:(g,2t+1) c2:(g+8,2t) c3:(g+8,2t+1)
#pragma unroll
    for (int nt = 0; nt < 4; nt++) {
        int col = bn + wn * 32 + nt * 8 + 2 * t;
        float bz0 = __ldg(&bias[col]);
        float bz1 = __ldg(&bias[col + 1]);
#pragma unroll
        for (int mt = 0; mt < 4; mt++) {
            int row0 = bm + wm * 64 + mt * 16 + g;
            float v0 = acc[mt][nt][0] + bz0;
            float v1 = acc[mt][nt][1] + bz1;
            float v2 = acc[mt][nt][2] + bz0;
            float v3 = acc[mt][nt][3] + bz1;
            if (relu) {
                v0 = fmaxf(v0, 0.f); v1 = fmaxf(v1, 0.f);
                v2 = fmaxf(v2, 0.f); v3 = fmaxf(v3, 0.f);
            }
            if (row0 < NN)
                *(__half2*)(C + (size_t)row0 * 256 + col) = __floats2half2_rn(v0, v1);
            if (row0 + 8 < NN)
                *(__half2*)(C + (size_t)(row0 + 8) * 256 + col) = __floats2half2_rn(v2, v3);
        }
    }
}

// ---------------- last layer projections + output init (fp32 weights) ----
__global__ void node_post_kernel(const __half* __restrict__ h,
                                 const float* __restrict__ rw3,
                                 const float* __restrict__ rb3,
                                 const float* __restrict__ sw3,
                                 float* __restrict__ out)
{
    int warp = (blockIdx.x * blockDim.x + threadIdx.x) >> 5;
    int lane = threadIdx.x & 31;
    if (warp >= NN) return;

    float pp[4] = {0.f, 0.f, 0.f, 0.f};
    float ss[4] = {0.f, 0.f, 0.f, 0.f};
#pragma unroll
    for (int j = 0; j < 8; j++) {
        int t = lane + 32 * j;
        float hv = __half2float(h[(size_t)warp * HID + t]);
#pragma unroll
        for (int c = 0; c < 4; c++) {
            pp[c] = fmaf(hv, __ldg(&rw3[t * 4 + c]), pp[c]);
            ss[c] = fmaf(hv, __ldg(&sw3[t * 4 + c]), ss[c]);
        }
    }
#pragma unroll
    for (int o = 16; o > 0; o >>= 1) {
#pragma unroll
        for (int c = 0; c < 4; c++) {
            pp[c] += __shfl_xor_sync(0xffffffffu, pp[c], o);
            ss[c] += __shfl_xor_sync(0xffffffffu, ss[c], o);
        }
    }
    if (lane == 0) {
        float cf = g_conf[warp];
        float om = 1.f - cf;
#pragma unroll
        for (int c = 0; c < 4; c++) {
            out[warp * 4 + c] = cf * g_weak[warp * 4 + c] + om * (ss[c] + __ldg(&rb3[c]));
            g_p3[warp * 4 + c] = pp[c];
        }
    }
}

// ---------------- final CSR gather: out[t] += (1-conf[t]) * sum p3[src] ----
__global__ void gather3_kernel(float* __restrict__ out)
{
    int t = blockIdx.x * blockDim.x + threadIdx.x;
    if (t >= NN) return;
    int beg = __ldg(&g_off[t]);
    int end = __ldg(&g_off[t + 1]);
    float4 s4 = make_float4(0.f, 0.f, 0.f, 0.f);
    for (int e = beg; e < end; e++) {
        int s = __ldg(&g_esrc[e]);
        float4 p = *(const float4*)&g_p3[s * 4];
        s4.x += p.x; s4.y += p.y; s4.z += p.z; s4.w += p.w;
    }
    float om = 1.f - g_conf[t];
    float4 o = *(float4*)&out[t * 4];
    o.x += om * s4.x; o.y += om * s4.y;
    o.z += om * s4.z; o.w += om * s4.w;
    *(float4*)&out[t * 4] = o;
}

// ---------------- host ----------------
extern "C" void kernel_launch(void* const* d_in, const int* in_sizes, int n_in,
                              void* d_out, int out_size)
{
    const float* x   = (const float*)d_in[0];
    const int* ei    = (const int*)d_in[1];   // int32 (JAX x64 disabled)
    const float* w1  = (const float*)d_in[2];
    const float* b1  = (const float*)d_in[3];
    const float* w2  = (const float*)d_in[4];
    const float* b2  = (const float*)d_in[5];
    const float* e1  = (const float*)d_in[6];
    const float* be1 = (const float*)d_in[7];
    const float* e2  = (const float*)d_in[8];
    const float* be2 = (const float*)d_in[9];
    const float* RW[3] = {(const float*)d_in[10], (const float*)d_in[13], (const float*)d_in[16]};
    const float* RB[3] = {(const float*)d_in[11], (const float*)d_in[14], (const float*)d_in[17]};
    const float* SW[3] = {(const float*)d_in[12], (const float*)d_in[15], (const float*)d_in[18]};
    const float* rw3 = (const float*)d_in[19];
    const float* rb3 = (const float*)d_in[20];
    const float* sw3 = (const float*)d_in[21];
    float* out = (float*)d_out;

    __half *h0, *h1, *hag, *wt;
    int* offp;
    cudaGetSymbolAddress((void**)&h0,  g_h0);
    cudaGetSymbolAddress((void**)&h1,  g_h1);
    cudaGetSymbolAddress((void**)&hag, g_hag);
    cudaGetSymbolAddress((void**)&wt,  g_wt);
    cudaGetSymbolAddress((void**)&offp, g_off);

    const int* src = ei;
    const int* tgt = ei + NE;

    // ---- CSR build ----
    zero_int_kernel<<<(NSCAN + 255) / 256, 256>>>(offp, NSCAN);
    hist_kernel<<<(NE + 255) / 256, 256>>>(tgt);
    scan_block_kernel<<<NBLK, SCAN_B>>>();
    scan_tot_kernel<<<1, 256>>>();
    scan_add_kernel<<<NBLK, SCAN_B>>>();
    fill_kernel<<<(NE + 255) / 256, 256>>>(src, tgt);

    // ---- weight prep + node stage 1 ----
    wprep_kernel<<<(7 * 65536 + 255) / 256, 256>>>(e2, RW[0], SW[0], RW[1], SW[1], RW[2], SW[2]);
    node_pre_kernel<<<(NN * 32 + 255) / 256, 256>>>(x, w1, b1, w2, b2, e1, be1);

    dim3 gg((NN + BM - 1) / BM, 256 / BN);
    gemm_tc_kernel<<<gg, 256>>>(h0, wt, nullptr, nullptr, be2, h1, 0, 0);

    __half* hcur = h1;
    __half* hnext = h0;
    for (int l = 0; l < 3; l++) {
        gather_kernel<<<(NN * 32 + 255) / 256, 256>>>(hcur, hag);
        gemm_tc_kernel<<<gg, 256>>>(hag, wt + (1 + 2 * l) * 65536,
                                    hcur, wt + (2 + 2 * l) * 65536,
                                    RB[l], hnext, 1, 1);
        __half* tmp = hcur; hcur = hnext; hnext = tmp;
    }

    node_post_kernel<<<(NN * 32 + 255) / 256, 256>>>(hcur, rw3, rb3, sw3, out);
    gather3_kernel<<<(NN + 255) / 256, 256>>>(out);
}